// round 1
// baseline (speedup 1.0000x reference)
#include <cuda_runtime.h>
#include <math.h>

// Problem constants
#define B_   4
#define L_   2048
#define E_   1024
#define H_   16
#define D_   64
#define MTOK (B_*L_)          // 8192 tokens
#define NEG_INF (-1.0e9f)
#define SCALE   0.125f        // 1/sqrt(64)

// ---------------------------------------------------------------------------
// Static device scratch (allocation-free rule: __device__ globals)
// ---------------------------------------------------------------------------
__device__ float g_Q[(size_t)MTOK * E_];     // [B,H,L,D]
__device__ float g_K[(size_t)MTOK * E_];     // [B,H,L,D]
__device__ float g_V[(size_t)MTOK * E_];     // [B,H,L,D]
__device__ float g_ctx[(size_t)MTOK * E_];   // [B*L, E]
// Fallback attention buffer in case out_size != o+attention concatenation
__device__ float g_att_fallback[(size_t)B_ * H_ * L_ * L_];

// ---------------------------------------------------------------------------
// Kernel 1/5: projection GEMM  C[M=8192,N=1024] = X @ W + bias
// SPLIT=1: scatter output to [B,H,L,D]; SPLIT=0: plain row-major [M,N]
// 128x128 block tile, BK=16, 256 threads, 8x8 microtile
// ---------------------------------------------------------------------------
template<int SPLIT>
__global__ __launch_bounds__(256)
void proj_gemm(const float* __restrict__ X, const float* __restrict__ W,
               const float* __restrict__ bias, float* __restrict__ out)
{
    __shared__ float As[16][132];   // [k][m], padded
    __shared__ float Bs[16][128];   // [k][n]
    const int tid = threadIdx.x;
    const int m0 = blockIdx.y * 128;
    const int n0 = blockIdx.x * 128;
    const int tr = tid >> 4;    // 0..15 (m)
    const int tc = tid & 15;    // 0..15 (n)

    float acc[8][8];
#pragma unroll
    for (int i = 0; i < 8; i++)
#pragma unroll
        for (int j = 0; j < 8; j++) acc[i][j] = 0.0f;

    for (int k0 = 0; k0 < E_; k0 += 16) {
#pragma unroll
        for (int t = 0; t < 2; t++) {
            int idx = tid + t * 256;
            // A tile: 128 rows x 16 k = 512 float4, 4 float4 per row
            int m  = idx >> 2;
            int kq = idx & 3;
            float4 va = *(const float4*)(X + (size_t)(m0 + m) * E_ + k0 + kq * 4);
            As[kq*4+0][m] = va.x; As[kq*4+1][m] = va.y;
            As[kq*4+2][m] = va.z; As[kq*4+3][m] = va.w;
            // B tile: 16 k x 128 n = 512 float4, 32 float4 per row
            int kb = idx >> 5;
            int nq = idx & 31;
            float4 vb = *(const float4*)(W + (size_t)(k0 + kb) * E_ + n0 + nq * 4);
            *(float4*)&Bs[kb][nq*4] = vb;
        }
        __syncthreads();
#pragma unroll
        for (int kk = 0; kk < 16; kk++) {
            float4 a0 = *(const float4*)&As[kk][tr*8];
            float4 a1 = *(const float4*)&As[kk][tr*8+4];
            float4 b0 = *(const float4*)&Bs[kk][tc*8];
            float4 b1 = *(const float4*)&Bs[kk][tc*8+4];
            float a[8] = {a0.x,a0.y,a0.z,a0.w,a1.x,a1.y,a1.z,a1.w};
            float b[8] = {b0.x,b0.y,b0.z,b0.w,b1.x,b1.y,b1.z,b1.w};
#pragma unroll
            for (int i = 0; i < 8; i++)
#pragma unroll
                for (int j = 0; j < 8; j++)
                    acc[i][j] = fmaf(a[i], b[j], acc[i][j]);
        }
        __syncthreads();
    }

    float bvals[8];
#pragma unroll
    for (int j = 0; j < 8; j++) bvals[j] = bias[n0 + tc*8 + j];

#pragma unroll
    for (int i = 0; i < 8; i++) {
        int m = m0 + tr*8 + i;
        int n = n0 + tc*8;
        float4 o0, o1;
        o0.x = acc[i][0]+bvals[0]; o0.y = acc[i][1]+bvals[1];
        o0.z = acc[i][2]+bvals[2]; o0.w = acc[i][3]+bvals[3];
        o1.x = acc[i][4]+bvals[4]; o1.y = acc[i][5]+bvals[5];
        o1.z = acc[i][6]+bvals[6]; o1.w = acc[i][7]+bvals[7];
        if (SPLIT) {
            int b = m >> 11;            // / L_
            int l = m & (L_ - 1);
            int h = n >> 6;             // / D_
            int d = n & (D_ - 1);
            float* dst = out + (((size_t)(b * H_ + h)) * L_ + l) * D_ + d;
            *(float4*)dst       = o0;
            *(float4*)(dst + 4) = o1;
        } else {
            float* dst = out + (size_t)m * E_ + n;
            *(float4*)dst       = o0;
            *(float4*)(dst + 4) = o1;
        }
    }
}

// ---------------------------------------------------------------------------
// Kernel 2/5: scores per head  S[q,k] = (Q K^T)*scale, masked, written to att
// 128x128 tile, full K-dim=64 in one shot, 256 threads, 8x8 microtile.
// Dynamic smem: Qs[64][132] + Ks[64][132]  (67584 bytes)
// ---------------------------------------------------------------------------
#define SCORES_SMEM (2 * 64 * 132 * (int)sizeof(float))

__global__ __launch_bounds__(256)
void scores_kernel(const float* __restrict__ Q, const float* __restrict__ Kmat,
                   const int* __restrict__ mask, float* __restrict__ att)
{
    extern __shared__ float sh[];
    float (*Qs)[132] = reinterpret_cast<float(*)[132]>(sh);
    float (*Ks)[132] = reinterpret_cast<float(*)[132]>(sh + 64 * 132);

    const int tid = threadIdx.x;
    const int bh  = blockIdx.z;
    const int b   = bh >> 4;            // / H_
    const int q0  = blockIdx.y * 128;
    const int k0  = blockIdx.x * 128;
    const float* Qb = Q    + (size_t)bh * L_ * D_;
    const float* Kb = Kmat + (size_t)bh * L_ * D_;

#pragma unroll
    for (int t = 0; t < 8; t++) {
        int idx = tid + t * 256;        // float4 index, tile = 128 rows x 16 float4
        int r  = idx >> 4;
        int dq = idx & 15;
        float4 va = *(const float4*)(Qb + (size_t)(q0 + r) * D_ + dq * 4);
        Qs[dq*4+0][r] = va.x; Qs[dq*4+1][r] = va.y;
        Qs[dq*4+2][r] = va.z; Qs[dq*4+3][r] = va.w;
        float4 vb = *(const float4*)(Kb + (size_t)(k0 + r) * D_ + dq * 4);
        Ks[dq*4+0][r] = vb.x; Ks[dq*4+1][r] = vb.y;
        Ks[dq*4+2][r] = vb.z; Ks[dq*4+3][r] = vb.w;
    }
    __syncthreads();

    const int tr = tid >> 4;
    const int tc = tid & 15;
    float acc[8][8];
#pragma unroll
    for (int i = 0; i < 8; i++)
#pragma unroll
        for (int j = 0; j < 8; j++) acc[i][j] = 0.0f;

#pragma unroll
    for (int d = 0; d < 64; d++) {
        float4 a0 = *(const float4*)&Qs[d][tr*8];
        float4 a1 = *(const float4*)&Qs[d][tr*8+4];
        float4 b0 = *(const float4*)&Ks[d][tc*8];
        float4 b1 = *(const float4*)&Ks[d][tc*8+4];
        float a[8] = {a0.x,a0.y,a0.z,a0.w,a1.x,a1.y,a1.z,a1.w};
        float b[8] = {b0.x,b0.y,b0.z,b0.w,b1.x,b1.y,b1.z,b1.w};
#pragma unroll
        for (int i = 0; i < 8; i++)
#pragma unroll
            for (int j = 0; j < 8; j++)
                acc[i][j] = fmaf(a[i], b[j], acc[i][j]);
    }

    const int*  mb = mask + (size_t)b  * L_ * L_;
    float*      ab = att  + (size_t)bh * L_ * L_;
#pragma unroll
    for (int i = 0; i < 8; i++) {
        int q = q0 + tr*8 + i;
        int k = k0 + tc*8;
        const size_t roff = (size_t)q * L_ + k;
        int4 m0v = *(const int4*)(mb + roff);
        int4 m1v = *(const int4*)(mb + roff + 4);
        float4 s0, s1;
        s0.x = m0v.x ? acc[i][0]*SCALE : NEG_INF;
        s0.y = m0v.y ? acc[i][1]*SCALE : NEG_INF;
        s0.z = m0v.z ? acc[i][2]*SCALE : NEG_INF;
        s0.w = m0v.w ? acc[i][3]*SCALE : NEG_INF;
        s1.x = m1v.x ? acc[i][4]*SCALE : NEG_INF;
        s1.y = m1v.y ? acc[i][5]*SCALE : NEG_INF;
        s1.z = m1v.z ? acc[i][6]*SCALE : NEG_INF;
        s1.w = m1v.w ? acc[i][7]*SCALE : NEG_INF;
        *(float4*)(ab + roff)     = s0;
        *(float4*)(ab + roff + 4) = s1;
    }
}

// ---------------------------------------------------------------------------
// Kernel 3/5: in-place row softmax over attention.  One CTA (256 thr) per row.
// ---------------------------------------------------------------------------
__global__ __launch_bounds__(256)
void softmax_kernel(float* __restrict__ att)
{
    float* p = att + (size_t)blockIdx.x * L_;
    const int tid = threadIdx.x;
    float4 v0 = ((const float4*)p)[tid];
    float4 v1 = ((const float4*)p)[tid + 256];

    float m = fmaxf(fmaxf(fmaxf(v0.x, v0.y), fmaxf(v0.z, v0.w)),
                    fmaxf(fmaxf(v1.x, v1.y), fmaxf(v1.z, v1.w)));
    __shared__ float red[8];
#pragma unroll
    for (int o = 16; o > 0; o >>= 1)
        m = fmaxf(m, __shfl_xor_sync(0xffffffffu, m, o));
    if ((tid & 31) == 0) red[tid >> 5] = m;
    __syncthreads();
    float rmax = red[0];
#pragma unroll
    for (int w = 1; w < 8; w++) rmax = fmaxf(rmax, red[w]);
    __syncthreads();

    v0.x = __expf(v0.x - rmax); v0.y = __expf(v0.y - rmax);
    v0.z = __expf(v0.z - rmax); v0.w = __expf(v0.w - rmax);
    v1.x = __expf(v1.x - rmax); v1.y = __expf(v1.y - rmax);
    v1.z = __expf(v1.z - rmax); v1.w = __expf(v1.w - rmax);
    float s = v0.x + v0.y + v0.z + v0.w + v1.x + v1.y + v1.z + v1.w;
#pragma unroll
    for (int o = 16; o > 0; o >>= 1)
        s += __shfl_xor_sync(0xffffffffu, s, o);
    if ((tid & 31) == 0) red[tid >> 5] = s;
    __syncthreads();
    float rsum = 0.0f;
#pragma unroll
    for (int w = 0; w < 8; w++) rsum += red[w];
    float inv = 1.0f / rsum;

    v0.x *= inv; v0.y *= inv; v0.z *= inv; v0.w *= inv;
    v1.x *= inv; v1.y *= inv; v1.z *= inv; v1.w *= inv;
    ((float4*)p)[tid]       = v0;
    ((float4*)p)[tid + 256] = v1;
}

// ---------------------------------------------------------------------------
// Kernel 4/5: AV per head  ctx[l, h*64+d] = sum_k P[l,k] V[k,d]
// 256x64 block tile, BK=32, 256 threads (32x8), 8x8 microtile
// ---------------------------------------------------------------------------
__global__ __launch_bounds__(256)
void av_kernel(const float* __restrict__ att, const float* __restrict__ V,
               float* __restrict__ ctx)
{
    __shared__ float As[32][260];   // [k][m], padded
    __shared__ float Bs[32][64];    // [k][d]
    const int tid = threadIdx.x;
    const int bh  = blockIdx.y;
    const int b   = bh >> 4;
    const int h   = bh & 15;
    const int m0  = blockIdx.x * 256;
    const float* Ab = att + (size_t)bh * L_ * L_;
    const float* Vb = V   + (size_t)bh * L_ * D_;
    const int tr = tid >> 3;    // 0..31 (m)
    const int tc = tid & 7;     // 0..7  (d)

    float acc[8][8];
#pragma unroll
    for (int i = 0; i < 8; i++)
#pragma unroll
        for (int j = 0; j < 8; j++) acc[i][j] = 0.0f;

    for (int k0 = 0; k0 < L_; k0 += 32) {
#pragma unroll
        for (int t = 0; t < 8; t++) {
            int idx = tid + t * 256;    // A tile: 256 rows x 8 float4 per row
            int r  = idx >> 3;
            int kq = idx & 7;
            float4 v = *(const float4*)(Ab + (size_t)(m0 + r) * L_ + k0 + kq * 4);
            As[kq*4+0][r] = v.x; As[kq*4+1][r] = v.y;
            As[kq*4+2][r] = v.z; As[kq*4+3][r] = v.w;
        }
#pragma unroll
        for (int t = 0; t < 2; t++) {
            int idx = tid + t * 256;    // B tile: 32 rows x 16 float4
            int kb = idx >> 4;
            int dq = idx & 15;
            *(float4*)&Bs[kb][dq*4] =
                *(const float4*)(Vb + (size_t)(k0 + kb) * D_ + dq * 4);
        }
        __syncthreads();
#pragma unroll
        for (int kk = 0; kk < 32; kk++) {
            float4 a0 = *(const float4*)&As[kk][tr*8];
            float4 a1 = *(const float4*)&As[kk][tr*8+4];
            float4 b0 = *(const float4*)&Bs[kk][tc*8];
            float4 b1 = *(const float4*)&Bs[kk][tc*8+4];
            float a[8] = {a0.x,a0.y,a0.z,a0.w,a1.x,a1.y,a1.z,a1.w};
            float bb[8] = {b0.x,b0.y,b0.z,b0.w,b1.x,b1.y,b1.z,b1.w};
#pragma unroll
            for (int i = 0; i < 8; i++)
#pragma unroll
                for (int j = 0; j < 8; j++)
                    acc[i][j] = fmaf(a[i], bb[j], acc[i][j]);
        }
        __syncthreads();
    }

#pragma unroll
    for (int i = 0; i < 8; i++) {
        int l = m0 + tr*8 + i;
        float* dst = ctx + ((size_t)b * L_ + l) * E_ + h * D_ + tc * 8;
        float4 o0, o1;
        o0.x = acc[i][0]; o0.y = acc[i][1]; o0.z = acc[i][2]; o0.w = acc[i][3];
        o1.x = acc[i][4]; o1.y = acc[i][5]; o1.z = acc[i][6]; o1.w = acc[i][7];
        *(float4*)dst       = o0;
        *(float4*)(dst + 4) = o1;
    }
}

// ---------------------------------------------------------------------------
// Launch
// ---------------------------------------------------------------------------
extern "C" void kernel_launch(void* const* d_in, const int* in_sizes, int n_in,
                              void* d_out, int out_size)
{
    const float* iq = (const float*)d_in[0];
    const float* ik = (const float*)d_in[1];
    const float* iv = (const float*)d_in[2];
    const int*   mk = (const int*)  d_in[3];
    const float* Wq = (const float*)d_in[4];
    const float* bq = (const float*)d_in[5];
    const float* Wk = (const float*)d_in[6];
    const float* bk = (const float*)d_in[7];
    const float* Wv = (const float*)d_in[8];
    const float* bv = (const float*)d_in[9];
    const float* Wo = (const float*)d_in[10];
    const float* bo = (const float*)d_in[11];

    float* o_out = (float*)d_out;
    const long long o_elems   = (long long)MTOK * E_;                  //   8,388,608
    const long long att_elems = (long long)B_ * H_ * L_ * L_;          // 268,435,456

    float *Qp, *Kp, *Vp, *Cp, *Ap;
    cudaGetSymbolAddress((void**)&Qp, g_Q);
    cudaGetSymbolAddress((void**)&Kp, g_K);
    cudaGetSymbolAddress((void**)&Vp, g_V);
    cudaGetSymbolAddress((void**)&Cp, g_ctx);
    cudaGetSymbolAddress((void**)&Ap, g_att_fallback);

    // Attention goes into d_out right after o if the output is the full tuple;
    // otherwise fall back to scratch so we never overflow d_out.
    float* att = ((long long)out_size >= o_elems + att_elems)
                     ? (o_out + o_elems) : Ap;

    cudaFuncSetAttribute(scores_kernel,
                         cudaFuncAttributeMaxDynamicSharedMemorySize, SCORES_SMEM);

    dim3 gp(E_ / 128, MTOK / 128);          // (8, 64)
    proj_gemm<1><<<gp, 256>>>(iq, Wq, bq, Qp);
    proj_gemm<1><<<gp, 256>>>(ik, Wk, bk, Kp);
    proj_gemm<1><<<gp, 256>>>(iv, Wv, bv, Vp);

    dim3 gs(L_ / 128, L_ / 128, B_ * H_);   // (16, 16, 64)
    scores_kernel<<<gs, 256, SCORES_SMEM>>>(Qp, Kp, mk, att);

    softmax_kernel<<<B_ * H_ * L_, 256>>>(att);

    dim3 ga(L_ / 256, B_ * H_);             // (8, 64)
    av_kernel<<<ga, 256>>>(att, Vp, Cp);

    proj_gemm<0><<<gp, 256>>>(Cp, Wo, bo, o_out);
}

// round 3
// speedup vs baseline: 1.0356x; 1.0356x over previous
#include <cuda_runtime.h>
#include <cuda_bf16.h>
#include <cstdint>

// Problem constants
#define B_   4
#define L_   2048
#define E_   1024
#define H_   16
#define D_   64
#define MTOK (B_*L_)
#define NEG_INF (-1.0e9f)
#define SCALE   0.125f

// ---------------------------------------------------------------------------
// Static device scratch
// ---------------------------------------------------------------------------
__device__ float g_Q[(size_t)MTOK * E_];     // [B,H,L,D] fp32
__device__ float g_K[(size_t)MTOK * E_];
__device__ float g_V[(size_t)MTOK * E_];
__device__ float g_ctx[(size_t)MTOK * E_];
__device__ float g_att_fallback[(size_t)B_ * H_ * L_ * L_];

// ---------------------------------------------------------------------------
// PTX helpers (compute_103-safe: ldmatrix + mma.sync only)
// ---------------------------------------------------------------------------
__device__ __forceinline__ uint32_t smem_u32(const void* p) {
    uint32_t a;
    asm("{ .reg .u64 t; cvta.to.shared.u64 t, %1; cvt.u32.u64 %0, t; }"
        : "=r"(a) : "l"(p));
    return a;
}

__device__ __forceinline__ void ldsm4(uint32_t* r, uint32_t a) {
    asm volatile("ldmatrix.sync.aligned.m8n8.x4.shared.b16 {%0,%1,%2,%3}, [%4];"
                 : "=r"(r[0]), "=r"(r[1]), "=r"(r[2]), "=r"(r[3]) : "r"(a));
}
__device__ __forceinline__ void ldsm2(uint32_t* r, uint32_t a) {
    asm volatile("ldmatrix.sync.aligned.m8n8.x2.shared.b16 {%0,%1}, [%2];"
                 : "=r"(r[0]), "=r"(r[1]) : "r"(a));
}
// D(16x8,f32) += A(16x16,bf16) * B(16x8,bf16)
__device__ __forceinline__ void mma16816(float* c, const uint32_t* a, const uint32_t* b) {
    asm volatile("mma.sync.aligned.m16n8k16.row.col.f32.bf16.bf16.f32 "
                 "{%0,%1,%2,%3}, {%4,%5,%6,%7}, {%8,%9}, {%0,%1,%2,%3};"
                 : "+f"(c[0]), "+f"(c[1]), "+f"(c[2]), "+f"(c[3])
                 : "r"(a[0]), "r"(a[1]), "r"(a[2]), "r"(a[3]), "r"(b[0]), "r"(b[1]));
}

// swizzled byte offset within a tile of 128-byte K-major rows
__device__ __forceinline__ uint32_t swz(int row, int colb) {
    uint32_t off = ((uint32_t)row << 7) + (uint32_t)colb;
    return off ^ (((uint32_t)row & 7u) << 4);
}

// ---------------------------------------------------------------------------
// Tile loaders: fp32 gmem -> split bf16 hi/lo smem (K-major 128B rows, swizzled)
// ---------------------------------------------------------------------------
__device__ __forceinline__ uint32_t pack_bf2(__nv_bfloat16 a, __nv_bfloat16 b) {
    return (uint32_t)__bfloat16_as_ushort(b) << 16 | (uint32_t)__bfloat16_as_ushort(a);
}

// [ROWS x 64] fp32 source, row stride lda
template<int ROWS>
__device__ __forceinline__ void load_kmajor(const float* __restrict__ src, int lda,
                                            char* sh, char* sl, int tid)
{
#pragma unroll
    for (int t = 0; t < ROWS * 16 / 256; t++) {
        int idx = tid + t * 256;
        int r = idx >> 4, q = idx & 15;
        float4 v = *(const float4*)(src + (size_t)r * lda + q * 4);
        __nv_bfloat16 h0 = __float2bfloat16(v.x), h1 = __float2bfloat16(v.y);
        __nv_bfloat16 h2 = __float2bfloat16(v.z), h3 = __float2bfloat16(v.w);
        __nv_bfloat16 l0 = __float2bfloat16(v.x - __bfloat162float(h0));
        __nv_bfloat16 l1 = __float2bfloat16(v.y - __bfloat162float(h1));
        __nv_bfloat16 l2 = __float2bfloat16(v.z - __bfloat162float(h2));
        __nv_bfloat16 l3 = __float2bfloat16(v.w - __bfloat162float(h3));
        uint32_t sw = swz(r, q * 8);
        uint2 ph; ph.x = pack_bf2(h0, h1); ph.y = pack_bf2(h2, h3);
        uint2 pl; pl.x = pack_bf2(l0, l1); pl.y = pack_bf2(l2, l3);
        *(uint2*)(sh + sw) = ph;
        *(uint2*)(sl + sw) = pl;
    }
}

// [BN x 64] <- transpose of 64 rows x BN cols (stride ldb)
template<int BN>
__device__ __forceinline__ void load_trans(const float* __restrict__ src, int ldb,
                                           char* sh, char* sl, int tid)
{
#pragma unroll
    for (int t = 0; t < 64 * (BN / 4) / 256; t++) {
        int idx = tid + t * 256;
        int kk = idx / (BN / 4);
        int n4 = idx % (BN / 4);
        float4 v = *(const float4*)(src + (size_t)kk * ldb + n4 * 4);
        float f[4] = {v.x, v.y, v.z, v.w};
#pragma unroll
        for (int j = 0; j < 4; j++) {
            int n = n4 * 4 + j;
            __nv_bfloat16 h = __float2bfloat16(f[j]);
            __nv_bfloat16 l = __float2bfloat16(f[j] - __bfloat162float(h));
            uint32_t sw = swz(n, kk * 2);
            *(__nv_bfloat16*)(sh + sw) = h;
            *(__nv_bfloat16*)(sl + sw) = l;
        }
    }
}

// ---------------------------------------------------------------------------
// Inner compute: one 64-wide K chunk, warp tile MF*16 x NF*8
// acc layout: acc[MF][NF][4]
// ---------------------------------------------------------------------------
template<int MF, int NF>
__device__ __forceinline__ void chunk_mma(float (*acc)[NF][4],
                                          uint32_t uAh, uint32_t uAl,
                                          uint32_t uBh, uint32_t uBl,
                                          int mw, int nw, int lane)
{
#pragma unroll
    for (int ks = 0; ks < 4; ks++) {
        uint32_t a_h[MF][4], a_l[MF][4], b_h[NF][2], b_l[NF][2];
        int acol = ks * 32 + ((lane >> 4) << 4);
        int bcol = ks * 32 + ((lane & 8) << 1);
#pragma unroll
        for (int mf = 0; mf < MF; mf++) {
            int r = mw + mf * 16 + (lane & 15);
            uint32_t sw = swz(r, acol);
            ldsm4(a_h[mf], uAh + sw);
            ldsm4(a_l[mf], uAl + sw);
        }
#pragma unroll
        for (int nf = 0; nf < NF; nf++) {
            int r = nw + nf * 8 + (lane & 7);
            uint32_t sw = swz(r, bcol);
            ldsm2(b_h[nf], uBh + sw);
            ldsm2(b_l[nf], uBl + sw);
        }
#pragma unroll
        for (int mf = 0; mf < MF; mf++)
#pragma unroll
            for (int nf = 0; nf < NF; nf++) {
                mma16816(acc[mf][nf], a_h[mf], b_h[nf]);
                mma16816(acc[mf][nf], a_h[mf], b_l[nf]);
                mma16816(acc[mf][nf], a_l[mf], b_h[nf]);
            }
    }
}

// ---------------------------------------------------------------------------
// Kernel 1: projection  C[8192x1024] = X @ W + bias  (block 128x128)
// smem: Ah|Al|Bh|Bl 16KB each = 64KB
// ---------------------------------------------------------------------------
#define PROJ_SMEM (4 * 16384)

template<int SPLIT>
__global__ __launch_bounds__(256)
void proj_mma(const float* __restrict__ X, const float* __restrict__ W,
              const float* __restrict__ bias, float* __restrict__ out)
{
    extern __shared__ char sm[];
    char* Ah = sm;
    char* Al = sm + 16384;
    char* Bh = sm + 32768;
    char* Bl = sm + 49152;
    const uint32_t uAh = smem_u32(Ah), uAl = uAh + 16384,
                   uBh = uAl + 16384, uBl = uBh + 16384;

    const int tid = threadIdx.x;
    const int wid = tid >> 5, lane = tid & 31;
    const int mw = (wid >> 2) * 64;     // warp m offset in tile
    const int nw = (wid & 3) * 32;      // warp n offset in tile
    const int n0 = blockIdx.x * 128;
    const int m0 = blockIdx.y * 128;

    float acc[4][4][4];
#pragma unroll
    for (int i = 0; i < 4; i++)
#pragma unroll
        for (int j = 0; j < 4; j++)
#pragma unroll
            for (int kk = 0; kk < 4; kk++) acc[i][j][kk] = 0.0f;

    for (int c = 0; c < 16; c++) {
        load_kmajor<128>(X + (size_t)m0 * E_ + c * 64, E_, Ah, Al, tid);
        load_trans<128>(W + (size_t)(c * 64) * E_ + n0, E_, Bh, Bl, tid);
        __syncthreads();
        chunk_mma<4, 4>(acc, uAh, uAl, uBh, uBl, mw, nw, lane);
        __syncthreads();
    }

    const int g = lane >> 2, tg = lane & 3;
#pragma unroll
    for (int mf = 0; mf < 4; mf++)
#pragma unroll
        for (int nf = 0; nf < 4; nf++) {
            int row = m0 + mw + mf * 16 + g;
            int col = n0 + nw + nf * 8 + tg * 2;
            float b0 = bias[col], b1 = bias[col + 1];
            float2 v0 = make_float2(acc[mf][nf][0] + b0, acc[mf][nf][1] + b1);
            float2 v1 = make_float2(acc[mf][nf][2] + b0, acc[mf][nf][3] + b1);
            if (SPLIT) {
                int b = row >> 11, l = row & (L_ - 1);
                int h = col >> 6, d = col & (D_ - 1);
                float* dst = out + (((size_t)(b * H_ + h)) * L_ + l) * D_ + d;
                *(float2*)dst            = v0;
                *(float2*)(dst + 8 * D_) = v1;
            } else {
                float* dst = out + (size_t)row * E_ + col;
                *(float2*)dst            = v0;
                *(float2*)(dst + 8 * E_) = v1;
            }
        }
}

// ---------------------------------------------------------------------------
// Kernel 2: scores  S = (Q K^T)*scale masked  (block 128q x 128k, one chunk)
// ---------------------------------------------------------------------------
#define SCORES_SMEM (4 * 16384)

__global__ __launch_bounds__(256)
void scores_mma(const float* __restrict__ Q, const float* __restrict__ Kmat,
                const int* __restrict__ mask, float* __restrict__ att)
{
    extern __shared__ char sm[];
    char* Ah = sm;
    char* Al = sm + 16384;
    char* Bh = sm + 32768;
    char* Bl = sm + 49152;
    const uint32_t uAh = smem_u32(Ah), uAl = uAh + 16384,
                   uBh = uAl + 16384, uBl = uBh + 16384;

    const int tid = threadIdx.x;
    const int wid = tid >> 5, lane = tid & 31;
    const int mw = (wid >> 2) * 64;
    const int nw = (wid & 3) * 32;
    const int k0 = blockIdx.x * 128;
    const int q0 = blockIdx.y * 128;
    const int bh = blockIdx.z;
    const int b  = bh >> 4;

    float acc[4][4][4];
#pragma unroll
    for (int i = 0; i < 4; i++)
#pragma unroll
        for (int j = 0; j < 4; j++)
#pragma unroll
            for (int kk = 0; kk < 4; kk++) acc[i][j][kk] = 0.0f;

    load_kmajor<128>(Q    + (size_t)bh * L_ * D_ + (size_t)q0 * D_, D_, Ah, Al, tid);
    load_kmajor<128>(Kmat + (size_t)bh * L_ * D_ + (size_t)k0 * D_, D_, Bh, Bl, tid);
    __syncthreads();
    chunk_mma<4, 4>(acc, uAh, uAl, uBh, uBl, mw, nw, lane);

    const int g = lane >> 2, tg = lane & 3;
    const int*  mb = mask + (size_t)b  * L_ * L_;
    float*      ab = att  + (size_t)bh * L_ * L_;
#pragma unroll
    for (int mf = 0; mf < 4; mf++)
#pragma unroll
        for (int nf = 0; nf < 4; nf++) {
            int q = q0 + mw + mf * 16 + g;
            int k = k0 + nw + nf * 8 + tg * 2;
            size_t o1 = (size_t)q * L_ + k;
            size_t o2 = o1 + 8 * (size_t)L_;
            int2 m1 = *(const int2*)(mb + o1);
            int2 m2 = *(const int2*)(mb + o2);
            float2 v1, v2;
            v1.x = m1.x ? acc[mf][nf][0] * SCALE : NEG_INF;
            v1.y = m1.y ? acc[mf][nf][1] * SCALE : NEG_INF;
            v2.x = m2.x ? acc[mf][nf][2] * SCALE : NEG_INF;
            v2.y = m2.y ? acc[mf][nf][3] * SCALE : NEG_INF;
            *(float2*)(ab + o1) = v1;
            *(float2*)(ab + o2) = v2;
        }
}

// ---------------------------------------------------------------------------
// Kernel 3: softmax (row of 2048, one CTA per row)
// ---------------------------------------------------------------------------
__global__ __launch_bounds__(256)
void softmax_kernel(float* __restrict__ att)
{
    float* p = att + (size_t)blockIdx.x * L_;
    const int tid = threadIdx.x;
    float4 v0 = ((const float4*)p)[tid];
    float4 v1 = ((const float4*)p)[tid + 256];

    float m = fmaxf(fmaxf(fmaxf(v0.x, v0.y), fmaxf(v0.z, v0.w)),
                    fmaxf(fmaxf(v1.x, v1.y), fmaxf(v1.z, v1.w)));
    __shared__ float red[8];
#pragma unroll
    for (int o = 16; o > 0; o >>= 1)
        m = fmaxf(m, __shfl_xor_sync(0xffffffffu, m, o));
    if ((tid & 31) == 0) red[tid >> 5] = m;
    __syncthreads();
    float rmax = red[0];
#pragma unroll
    for (int w = 1; w < 8; w++) rmax = fmaxf(rmax, red[w]);
    __syncthreads();

    v0.x = __expf(v0.x - rmax); v0.y = __expf(v0.y - rmax);
    v0.z = __expf(v0.z - rmax); v0.w = __expf(v0.w - rmax);
    v1.x = __expf(v1.x - rmax); v1.y = __expf(v1.y - rmax);
    v1.z = __expf(v1.z - rmax); v1.w = __expf(v1.w - rmax);
    float s = v0.x + v0.y + v0.z + v0.w + v1.x + v1.y + v1.z + v1.w;
#pragma unroll
    for (int o = 16; o > 0; o >>= 1)
        s += __shfl_xor_sync(0xffffffffu, s, o);
    if ((tid & 31) == 0) red[tid >> 5] = s;
    __syncthreads();
    float rsum = 0.0f;
#pragma unroll
    for (int w = 0; w < 8; w++) rsum += red[w];
    float inv = 1.0f / rsum;

    v0.x *= inv; v0.y *= inv; v0.z *= inv; v0.w *= inv;
    v1.x *= inv; v1.y *= inv; v1.z *= inv; v1.w *= inv;
    ((float4*)p)[tid]       = v0;
    ((float4*)p)[tid + 256] = v1;
}

// ---------------------------------------------------------------------------
// Kernel 4: AV  ctx = P @ V  (block 128m x 64d, 32 chunks)
// smem: Ah|Al 16KB, Bh|Bl 8KB = 48KB
// ---------------------------------------------------------------------------
#define AV_SMEM (2 * 16384 + 2 * 8192)

__global__ __launch_bounds__(256)
void av_mma(const float* __restrict__ att, const float* __restrict__ V,
            float* __restrict__ ctx)
{
    extern __shared__ char sm[];
    char* Ah = sm;
    char* Al = sm + 16384;
    char* Bh = sm + 32768;
    char* Bl = sm + 40960;
    const uint32_t uAh = smem_u32(Ah), uAl = uAh + 16384,
                   uBh = uAl + 16384, uBl = uBh + 8192;

    const int tid = threadIdx.x;
    const int wid = tid >> 5, lane = tid & 31;
    const int mw = (wid >> 1) * 32;     // 4 warps in m
    const int nw = (wid & 1) * 32;      // 2 warps in n
    const int m0 = blockIdx.x * 128;
    const int bh = blockIdx.y;
    const int b  = bh >> 4, h = bh & 15;

    const float* Ab = att + (size_t)bh * L_ * L_ + (size_t)m0 * L_;
    const float* Vb = V   + (size_t)bh * L_ * D_;

    float acc[2][4][4];
#pragma unroll
    for (int i = 0; i < 2; i++)
#pragma unroll
        for (int j = 0; j < 4; j++)
#pragma unroll
            for (int kk = 0; kk < 4; kk++) acc[i][j][kk] = 0.0f;

    for (int c = 0; c < 32; c++) {
        load_kmajor<128>(Ab + c * 64, L_, Ah, Al, tid);
        load_trans<64>(Vb + (size_t)(c * 64) * D_, D_, Bh, Bl, tid);
        __syncthreads();
        chunk_mma<2, 4>(acc, uAh, uAl, uBh, uBl, mw, nw, lane);
        __syncthreads();
    }

    const int g = lane >> 2, tg = lane & 3;
#pragma unroll
    for (int mf = 0; mf < 2; mf++)
#pragma unroll
        for (int nf = 0; nf < 4; nf++) {
            int m   = m0 + mw + mf * 16 + g;
            int col = nw + nf * 8 + tg * 2;
            float* dst = ctx + ((size_t)b * L_ + m) * E_ + h * D_ + col;
            *(float2*)dst            = make_float2(acc[mf][nf][0], acc[mf][nf][1]);
            *(float2*)(dst + 8 * E_) = make_float2(acc[mf][nf][2], acc[mf][nf][3]);
        }
}

// ---------------------------------------------------------------------------
// Launch
// ---------------------------------------------------------------------------
extern "C" void kernel_launch(void* const* d_in, const int* in_sizes, int n_in,
                              void* d_out, int out_size)
{
    const float* iq = (const float*)d_in[0];
    const float* ik = (const float*)d_in[1];
    const float* iv = (const float*)d_in[2];
    const int*   mk = (const int*)  d_in[3];
    const float* Wq = (const float*)d_in[4];
    const float* bq = (const float*)d_in[5];
    const float* Wk = (const float*)d_in[6];
    const float* bk = (const float*)d_in[7];
    const float* Wv = (const float*)d_in[8];
    const float* bv = (const float*)d_in[9];
    const float* Wo = (const float*)d_in[10];
    const float* bo = (const float*)d_in[11];

    float* o_out = (float*)d_out;
    const long long o_elems   = (long long)MTOK * E_;
    const long long att_elems = (long long)B_ * H_ * L_ * L_;

    float *Qp, *Kp, *Vp, *Cp, *Ap;
    cudaGetSymbolAddress((void**)&Qp, g_Q);
    cudaGetSymbolAddress((void**)&Kp, g_K);
    cudaGetSymbolAddress((void**)&Vp, g_V);
    cudaGetSymbolAddress((void**)&Cp, g_ctx);
    cudaGetSymbolAddress((void**)&Ap, g_att_fallback);

    float* att = ((long long)out_size >= o_elems + att_elems)
                     ? (o_out + o_elems) : Ap;

    cudaFuncSetAttribute(proj_mma<1>, cudaFuncAttributeMaxDynamicSharedMemorySize, PROJ_SMEM);
    cudaFuncSetAttribute(proj_mma<0>, cudaFuncAttributeMaxDynamicSharedMemorySize, PROJ_SMEM);
    cudaFuncSetAttribute(scores_mma,  cudaFuncAttributeMaxDynamicSharedMemorySize, SCORES_SMEM);
    cudaFuncSetAttribute(av_mma,      cudaFuncAttributeMaxDynamicSharedMemorySize, AV_SMEM);

    dim3 gp(E_ / 128, MTOK / 128);              // (8, 64)
    proj_mma<1><<<gp, 256, PROJ_SMEM>>>(iq, Wq, bq, Qp);
    proj_mma<1><<<gp, 256, PROJ_SMEM>>>(ik, Wk, bk, Kp);
    proj_mma<1><<<gp, 256, PROJ_SMEM>>>(iv, Wv, bv, Vp);

    dim3 gs(L_ / 128, L_ / 128, B_ * H_);       // (16, 16, 64)
    scores_mma<<<gs, 256, SCORES_SMEM>>>(Qp, Kp, mk, att);

    softmax_kernel<<<B_ * H_ * L_, 256>>>(att);

    dim3 ga(L_ / 128, B_ * H_);                 // (16, 64)
    av_mma<<<ga, 256, AV_SMEM>>>(att, Vp, Cp);

    proj_mma<0><<<gp, 256, PROJ_SMEM>>>(Cp, Wo, bo, o_out);
}

// round 4
// speedup vs baseline: 1.4630x; 1.4126x over previous
#include <cuda_runtime.h>
#include <cuda_bf16.h>
#include <cstdint>

// Problem constants
#define B_   4
#define L_   2048
#define E_   1024
#define H_   16
#define D_   64
#define MTOK (B_*L_)
#define NEG_INF (-1.0e9f)
#define SCALE   0.125f

// ---------------------------------------------------------------------------
// Static device scratch
// ---------------------------------------------------------------------------
__device__ float g_Q[(size_t)MTOK * E_];     // [B,H,L,D] fp32
__device__ float g_K[(size_t)MTOK * E_];
__device__ float g_V[(size_t)MTOK * E_];
__device__ float g_ctx[(size_t)MTOK * E_];
__device__ float g_att_fallback[(size_t)B_ * H_ * L_ * L_];

// ---------------------------------------------------------------------------
// PTX helpers (compute_103-safe: ldmatrix + mma.sync only)
// ---------------------------------------------------------------------------
__device__ __forceinline__ uint32_t smem_u32(const void* p) {
    uint32_t a;
    asm("{ .reg .u64 t; cvta.to.shared.u64 t, %1; cvt.u32.u64 %0, t; }"
        : "=r"(a) : "l"(p));
    return a;
}

__device__ __forceinline__ void ldsm4(uint32_t* r, uint32_t a) {
    asm volatile("ldmatrix.sync.aligned.m8n8.x4.shared.b16 {%0,%1,%2,%3}, [%4];"
                 : "=r"(r[0]), "=r"(r[1]), "=r"(r[2]), "=r"(r[3]) : "r"(a));
}
__device__ __forceinline__ void ldsm2(uint32_t* r, uint32_t a) {
    asm volatile("ldmatrix.sync.aligned.m8n8.x2.shared.b16 {%0,%1}, [%2];"
                 : "=r"(r[0]), "=r"(r[1]) : "r"(a));
}
// D(16x8,f32) += A(16x16,bf16) * B(16x8,bf16)
__device__ __forceinline__ void mma16816(float* c, const uint32_t* a, const uint32_t* b) {
    asm volatile("mma.sync.aligned.m16n8k16.row.col.f32.bf16.bf16.f32 "
                 "{%0,%1,%2,%3}, {%4,%5,%6,%7}, {%8,%9}, {%0,%1,%2,%3};"
                 : "+f"(c[0]), "+f"(c[1]), "+f"(c[2]), "+f"(c[3])
                 : "r"(a[0]), "r"(a[1]), "r"(a[2]), "r"(a[3]), "r"(b[0]), "r"(b[1]));
}

// swizzled byte offset within a tile of 128-byte K-major rows
__device__ __forceinline__ uint32_t swz(int row, int colb) {
    uint32_t off = ((uint32_t)row << 7) + (uint32_t)colb;
    return off ^ (((uint32_t)row & 7u) << 4);
}

// ---------------------------------------------------------------------------
// Tile loaders: fp32 gmem -> split bf16 hi/lo smem (K-major 128B rows, swizzled)
// ---------------------------------------------------------------------------
__device__ __forceinline__ uint32_t pack_bf2(__nv_bfloat16 a, __nv_bfloat16 b) {
    return (uint32_t)__bfloat16_as_ushort(b) << 16 | (uint32_t)__bfloat16_as_ushort(a);
}

// [ROWS x 64] fp32 source, row stride lda
template<int ROWS>
__device__ __forceinline__ void load_kmajor(const float* __restrict__ src, int lda,
                                            char* sh, char* sl, int tid)
{
#pragma unroll
    for (int t = 0; t < ROWS * 16 / 256; t++) {
        int idx = tid + t * 256;
        int r = idx >> 4, q = idx & 15;
        float4 v = *(const float4*)(src + (size_t)r * lda + q * 4);
        __nv_bfloat16 h0 = __float2bfloat16(v.x), h1 = __float2bfloat16(v.y);
        __nv_bfloat16 h2 = __float2bfloat16(v.z), h3 = __float2bfloat16(v.w);
        __nv_bfloat16 l0 = __float2bfloat16(v.x - __bfloat162float(h0));
        __nv_bfloat16 l1 = __float2bfloat16(v.y - __bfloat162float(h1));
        __nv_bfloat16 l2 = __float2bfloat16(v.z - __bfloat162float(h2));
        __nv_bfloat16 l3 = __float2bfloat16(v.w - __bfloat162float(h3));
        uint32_t sw = swz(r, q * 8);
        uint2 ph; ph.x = pack_bf2(h0, h1); ph.y = pack_bf2(h2, h3);
        uint2 pl; pl.x = pack_bf2(l0, l1); pl.y = pack_bf2(l2, l3);
        *(uint2*)(sh + sw) = ph;
        *(uint2*)(sl + sw) = pl;
    }
}

// [BN x 64] <- transpose of 64 rows x BN cols (stride ldb)
template<int BN>
__device__ __forceinline__ void load_trans(const float* __restrict__ src, int ldb,
                                           char* sh, char* sl, int tid)
{
#pragma unroll
    for (int t = 0; t < 64 * (BN / 4) / 256; t++) {
        int idx = tid + t * 256;
        int kk = idx / (BN / 4);
        int n4 = idx % (BN / 4);
        float4 v = *(const float4*)(src + (size_t)kk * ldb + n4 * 4);
        float f[4] = {v.x, v.y, v.z, v.w};
#pragma unroll
        for (int j = 0; j < 4; j++) {
            int n = n4 * 4 + j;
            __nv_bfloat16 h = __float2bfloat16(f[j]);
            __nv_bfloat16 l = __float2bfloat16(f[j] - __bfloat162float(h));
            uint32_t sw = swz(n, kk * 2);
            *(__nv_bfloat16*)(sh + sw) = h;
            *(__nv_bfloat16*)(sl + sw) = l;
        }
    }
}

// ---------------------------------------------------------------------------
// Inner compute: one 64-wide K chunk, warp tile 32x32 (MF=2, NF=4)
// 8 warps: 4 in m (128 rows), 2 in n (64 cols)
// ---------------------------------------------------------------------------
#define MF 2
#define NF 4

__device__ __forceinline__ void chunk_mma(float (*acc)[NF][4],
                                          uint32_t uAh, uint32_t uAl,
                                          uint32_t uBh, uint32_t uBl,
                                          int mw, int nw, int lane)
{
#pragma unroll
    for (int ks = 0; ks < 4; ks++) {
        uint32_t a_h[MF][4], a_l[MF][4], b_h[NF][2], b_l[NF][2];
        int acol = ks * 32 + ((lane >> 4) << 4);
        int bcol = ks * 32 + ((lane & 8) << 1);
#pragma unroll
        for (int mf = 0; mf < MF; mf++) {
            int r = mw + mf * 16 + (lane & 15);
            uint32_t sw = swz(r, acol);
            ldsm4(a_h[mf], uAh + sw);
            ldsm4(a_l[mf], uAl + sw);
        }
#pragma unroll
        for (int nf = 0; nf < NF; nf++) {
            int r = nw + nf * 8 + (lane & 7);
            uint32_t sw = swz(r, bcol);
            ldsm2(b_h[nf], uBh + sw);
            ldsm2(b_l[nf], uBl + sw);
        }
#pragma unroll
        for (int mf = 0; mf < MF; mf++)
#pragma unroll
            for (int nf = 0; nf < NF; nf++) {
                mma16816(acc[mf][nf], a_h[mf], b_h[nf]);
                mma16816(acc[mf][nf], a_h[mf], b_l[nf]);
                mma16816(acc[mf][nf], a_l[mf], b_h[nf]);
            }
    }
}

// ---------------------------------------------------------------------------
// Kernel 1: projection  C[8192x1024] = X @ W + bias  (block 128m x 64n)
// smem: Ah|Al 16KB, Bh|Bl 8KB = 48KB
// ---------------------------------------------------------------------------
#define GEMM_SMEM (2 * 16384 + 2 * 8192)

template<int SPLIT>
__global__ __launch_bounds__(256, 2)
void proj_mma(const float* __restrict__ X, const float* __restrict__ W,
              const float* __restrict__ bias, float* __restrict__ out)
{
    extern __shared__ char sm[];
    char* Ah = sm;
    char* Al = sm + 16384;
    char* Bh = sm + 32768;
    char* Bl = sm + 40960;
    const uint32_t uAh = smem_u32(Ah), uAl = uAh + 16384,
                   uBh = uAl + 16384, uBl = uBh + 8192;

    const int tid = threadIdx.x;
    const int wid = tid >> 5, lane = tid & 31;
    const int mw = (wid >> 1) * 32;     // 4 warps in m
    const int nw = (wid & 1) * 32;      // 2 warps in n
    const int n0 = blockIdx.x * 64;
    const int m0 = blockIdx.y * 128;

    float acc[MF][NF][4];
#pragma unroll
    for (int i = 0; i < MF; i++)
#pragma unroll
        for (int j = 0; j < NF; j++)
#pragma unroll
            for (int kk = 0; kk < 4; kk++) acc[i][j][kk] = 0.0f;

    for (int c = 0; c < 16; c++) {
        load_kmajor<128>(X + (size_t)m0 * E_ + c * 64, E_, Ah, Al, tid);
        load_trans<64>(W + (size_t)(c * 64) * E_ + n0, E_, Bh, Bl, tid);
        __syncthreads();
        chunk_mma(acc, uAh, uAl, uBh, uBl, mw, nw, lane);
        __syncthreads();
    }

    const int g = lane >> 2, tg = lane & 3;
#pragma unroll
    for (int mf = 0; mf < MF; mf++)
#pragma unroll
        for (int nf = 0; nf < NF; nf++) {
            int row = m0 + mw + mf * 16 + g;
            int col = n0 + nw + nf * 8 + tg * 2;
            float b0 = bias[col], b1 = bias[col + 1];
            float2 v0 = make_float2(acc[mf][nf][0] + b0, acc[mf][nf][1] + b1);
            float2 v1 = make_float2(acc[mf][nf][2] + b0, acc[mf][nf][3] + b1);
            if (SPLIT) {
                int b = row >> 11, l = row & (L_ - 1);
                int h = col >> 6, d = col & (D_ - 1);
                float* dst = out + (((size_t)(b * H_ + h)) * L_ + l) * D_ + d;
                *(float2*)dst            = v0;
                *(float2*)(dst + 8 * D_) = v1;
            } else {
                float* dst = out + (size_t)row * E_ + col;
                *(float2*)dst            = v0;
                *(float2*)(dst + 8 * E_) = v1;
            }
        }
}

// ---------------------------------------------------------------------------
// Kernel 2: scores  S = (Q K^T)*scale masked  (block 128q, loops all 2048 k)
// Q tile persistent in smem; K tile reloaded per 64-wide k-block.
// ---------------------------------------------------------------------------
__global__ __launch_bounds__(256, 2)
void scores_mma(const float* __restrict__ Q, const float* __restrict__ Kmat,
                const int* __restrict__ mask, float* __restrict__ att)
{
    extern __shared__ char sm[];
    char* Ah = sm;
    char* Al = sm + 16384;
    char* Bh = sm + 32768;
    char* Bl = sm + 40960;
    const uint32_t uAh = smem_u32(Ah), uAl = uAh + 16384,
                   uBh = uAl + 16384, uBl = uBh + 8192;

    const int tid = threadIdx.x;
    const int wid = tid >> 5, lane = tid & 31;
    const int mw = (wid >> 1) * 32;
    const int nw = (wid & 1) * 32;
    const int q0 = blockIdx.x * 128;
    const int bh = blockIdx.y;
    const int b  = bh >> 4;
    const int g = lane >> 2, tg = lane & 3;

    const float* Kb = Kmat + (size_t)bh * L_ * D_;
    const int*   mb = mask + (size_t)b  * L_ * L_;
    float*       ab = att  + (size_t)bh * L_ * L_;

    // persistent Q tile
    load_kmajor<128>(Q + (size_t)bh * L_ * D_ + (size_t)q0 * D_, D_, Ah, Al, tid);

    for (int kt = 0; kt < 32; kt++) {
        const int k0 = kt * 64;
        load_kmajor<64>(Kb + (size_t)k0 * D_, D_, Bh, Bl, tid);
        __syncthreads();

        float acc[MF][NF][4];
#pragma unroll
        for (int i = 0; i < MF; i++)
#pragma unroll
            for (int j = 0; j < NF; j++)
#pragma unroll
                for (int kk = 0; kk < 4; kk++) acc[i][j][kk] = 0.0f;

        chunk_mma(acc, uAh, uAl, uBh, uBl, mw, nw, lane);
        __syncthreads();   // B consumed; epilogue overlaps next load

#pragma unroll
        for (int mf = 0; mf < MF; mf++)
#pragma unroll
            for (int nf = 0; nf < NF; nf++) {
                int q = q0 + mw + mf * 16 + g;
                int k = k0 + nw + nf * 8 + tg * 2;
                size_t o1 = (size_t)q * L_ + k;
                size_t o2 = o1 + 8 * (size_t)L_;
                int2 m1 = *(const int2*)(mb + o1);
                int2 m2 = *(const int2*)(mb + o2);
                float2 v1, v2;
                v1.x = m1.x ? acc[mf][nf][0] * SCALE : NEG_INF;
                v1.y = m1.y ? acc[mf][nf][1] * SCALE : NEG_INF;
                v2.x = m2.x ? acc[mf][nf][2] * SCALE : NEG_INF;
                v2.y = m2.y ? acc[mf][nf][3] * SCALE : NEG_INF;
                *(float2*)(ab + o1) = v1;
                *(float2*)(ab + o2) = v2;
            }
    }
}

// ---------------------------------------------------------------------------
// Kernel 3: softmax (row of 2048, one CTA per row)
// ---------------------------------------------------------------------------
__global__ __launch_bounds__(256)
void softmax_kernel(float* __restrict__ att)
{
    float* p = att + (size_t)blockIdx.x * L_;
    const int tid = threadIdx.x;
    float4 v0 = ((const float4*)p)[tid];
    float4 v1 = ((const float4*)p)[tid + 256];

    float m = fmaxf(fmaxf(fmaxf(v0.x, v0.y), fmaxf(v0.z, v0.w)),
                    fmaxf(fmaxf(v1.x, v1.y), fmaxf(v1.z, v1.w)));
    __shared__ float red[8];
#pragma unroll
    for (int o = 16; o > 0; o >>= 1)
        m = fmaxf(m, __shfl_xor_sync(0xffffffffu, m, o));
    if ((tid & 31) == 0) red[tid >> 5] = m;
    __syncthreads();
    float rmax = red[0];
#pragma unroll
    for (int w = 1; w < 8; w++) rmax = fmaxf(rmax, red[w]);
    __syncthreads();

    v0.x = __expf(v0.x - rmax); v0.y = __expf(v0.y - rmax);
    v0.z = __expf(v0.z - rmax); v0.w = __expf(v0.w - rmax);
    v1.x = __expf(v1.x - rmax); v1.y = __expf(v1.y - rmax);
    v1.z = __expf(v1.z - rmax); v1.w = __expf(v1.w - rmax);
    float s = v0.x + v0.y + v0.z + v0.w + v1.x + v1.y + v1.z + v1.w;
#pragma unroll
    for (int o = 16; o > 0; o >>= 1)
        s += __shfl_xor_sync(0xffffffffu, s, o);
    if ((tid & 31) == 0) red[tid >> 5] = s;
    __syncthreads();
    float rsum = 0.0f;
#pragma unroll
    for (int w = 0; w < 8; w++) rsum += red[w];
    float inv = 1.0f / rsum;

    v0.x *= inv; v0.y *= inv; v0.z *= inv; v0.w *= inv;
    v1.x *= inv; v1.y *= inv; v1.z *= inv; v1.w *= inv;
    ((float4*)p)[tid]       = v0;
    ((float4*)p)[tid + 256] = v1;
}

// ---------------------------------------------------------------------------
// Kernel 4: AV  ctx = P @ V  (block 128m x 64d, 32 chunks)
// ---------------------------------------------------------------------------
__global__ __launch_bounds__(256, 2)
void av_mma(const float* __restrict__ att, const float* __restrict__ V,
            float* __restrict__ ctx)
{
    extern __shared__ char sm[];
    char* Ah = sm;
    char* Al = sm + 16384;
    char* Bh = sm + 32768;
    char* Bl = sm + 40960;
    const uint32_t uAh = smem_u32(Ah), uAl = uAh + 16384,
                   uBh = uAl + 16384, uBl = uBh + 8192;

    const int tid = threadIdx.x;
    const int wid = tid >> 5, lane = tid & 31;
    const int mw = (wid >> 1) * 32;
    const int nw = (wid & 1) * 32;
    const int m0 = blockIdx.x * 128;
    const int bh = blockIdx.y;
    const int b  = bh >> 4, h = bh & 15;

    const float* Ab = att + (size_t)bh * L_ * L_ + (size_t)m0 * L_;
    const float* Vb = V   + (size_t)bh * L_ * D_;

    float acc[MF][NF][4];
#pragma unroll
    for (int i = 0; i < MF; i++)
#pragma unroll
        for (int j = 0; j < NF; j++)
#pragma unroll
            for (int kk = 0; kk < 4; kk++) acc[i][j][kk] = 0.0f;

    for (int c = 0; c < 32; c++) {
        load_kmajor<128>(Ab + c * 64, L_, Ah, Al, tid);
        load_trans<64>(Vb + (size_t)(c * 64) * D_, D_, Bh, Bl, tid);
        __syncthreads();
        chunk_mma(acc, uAh, uAl, uBh, uBl, mw, nw, lane);
        __syncthreads();
    }

    const int g = lane >> 2, tg = lane & 3;
#pragma unroll
    for (int mf = 0; mf < MF; mf++)
#pragma unroll
        for (int nf = 0; nf < NF; nf++) {
            int m   = m0 + mw + mf * 16 + g;
            int col = nw + nf * 8 + tg * 2;
            float* dst = ctx + ((size_t)b * L_ + m) * E_ + h * D_ + col;
            *(float2*)dst            = make_float2(acc[mf][nf][0], acc[mf][nf][1]);
            *(float2*)(dst + 8 * E_) = make_float2(acc[mf][nf][2], acc[mf][nf][3]);
        }
}

// ---------------------------------------------------------------------------
// Launch
// ---------------------------------------------------------------------------
extern "C" void kernel_launch(void* const* d_in, const int* in_sizes, int n_in,
                              void* d_out, int out_size)
{
    const float* iq = (const float*)d_in[0];
    const float* ik = (const float*)d_in[1];
    const float* iv = (const float*)d_in[2];
    const int*   mk = (const int*)  d_in[3];
    const float* Wq = (const float*)d_in[4];
    const float* bq = (const float*)d_in[5];
    const float* Wk = (const float*)d_in[6];
    const float* bk = (const float*)d_in[7];
    const float* Wv = (const float*)d_in[8];
    const float* bv = (const float*)d_in[9];
    const float* Wo = (const float*)d_in[10];
    const float* bo = (const float*)d_in[11];

    float* o_out = (float*)d_out;
    const long long o_elems   = (long long)MTOK * E_;
    const long long att_elems = (long long)B_ * H_ * L_ * L_;

    float *Qp, *Kp, *Vp, *Cp, *Ap;
    cudaGetSymbolAddress((void**)&Qp, g_Q);
    cudaGetSymbolAddress((void**)&Kp, g_K);
    cudaGetSymbolAddress((void**)&Vp, g_V);
    cudaGetSymbolAddress((void**)&Cp, g_ctx);
    cudaGetSymbolAddress((void**)&Ap, g_att_fallback);

    float* att = ((long long)out_size >= o_elems + att_elems)
                     ? (o_out + o_elems) : Ap;

    cudaFuncSetAttribute(proj_mma<1>, cudaFuncAttributeMaxDynamicSharedMemorySize, GEMM_SMEM);
    cudaFuncSetAttribute(proj_mma<0>, cudaFuncAttributeMaxDynamicSharedMemorySize, GEMM_SMEM);
    cudaFuncSetAttribute(scores_mma,  cudaFuncAttributeMaxDynamicSharedMemorySize, GEMM_SMEM);
    cudaFuncSetAttribute(av_mma,      cudaFuncAttributeMaxDynamicSharedMemorySize, GEMM_SMEM);

    dim3 gp(E_ / 64, MTOK / 128);               // (16, 64)
    proj_mma<1><<<gp, 256, GEMM_SMEM>>>(iq, Wq, bq, Qp);
    proj_mma<1><<<gp, 256, GEMM_SMEM>>>(ik, Wk, bk, Kp);
    proj_mma<1><<<gp, 256, GEMM_SMEM>>>(iv, Wv, bv, Vp);

    dim3 gs(L_ / 128, B_ * H_);                 // (16, 64)
    scores_mma<<<gs, 256, GEMM_SMEM>>>(Qp, Kp, mk, att);

    softmax_kernel<<<B_ * H_ * L_, 256>>>(att);

    dim3 ga(L_ / 128, B_ * H_);                 // (16, 64)
    av_mma<<<ga, 256, GEMM_SMEM>>>(att, Vp, Cp);

    proj_mma<0><<<gp, 256, GEMM_SMEM>>>(Cp, Wo, bo, o_out);
}

// round 5
// speedup vs baseline: 2.2809x; 1.5591x over previous
#include <cuda_runtime.h>
#include <cuda_bf16.h>
#include <cstdint>

// Problem constants
#define B_   4
#define L_   2048
#define E_   1024
#define H_   16
#define D_   64
#define MTOK (B_*L_)
#define NEG_INF (-1.0e9f)
#define SCALE   0.125f

typedef __nv_bfloat16 bf16;

// ---------------------------------------------------------------------------
// Static device scratch (bf16 hi/lo operand copies)
// ---------------------------------------------------------------------------
__device__ bf16 g_Qh[(size_t)MTOK * E_], g_Ql[(size_t)MTOK * E_];   // [bh][l][64]
__device__ bf16 g_Kh[(size_t)MTOK * E_], g_Kl[(size_t)MTOK * E_];
__device__ bf16 g_Vh[(size_t)MTOK * E_], g_Vl[(size_t)MTOK * E_];
__device__ bf16 g_Xh[(size_t)MTOK * E_], g_Xl[(size_t)MTOK * E_];   // input staging
__device__ bf16 g_Wh[(size_t)E_ * E_],   g_Wl[(size_t)E_ * E_];     // weight staging
__device__ bf16 g_Ch[(size_t)MTOK * E_], g_Cl[(size_t)MTOK * E_];   // ctx
__device__ float g_att_fallback[(size_t)B_ * H_ * L_ * L_];

// ---------------------------------------------------------------------------
// PTX helpers
// ---------------------------------------------------------------------------
__device__ __forceinline__ uint32_t smem_u32(const void* p) {
    uint32_t a;
    asm("{ .reg .u64 t; cvta.to.shared.u64 t, %1; cvt.u32.u64 %0, t; }"
        : "=r"(a) : "l"(p));
    return a;
}
__device__ __forceinline__ void cp16(uint32_t dst, const void* src) {
    asm volatile("cp.async.cg.shared.global [%0], [%1], 16;" :: "r"(dst), "l"(src));
}
#define CP_COMMIT() asm volatile("cp.async.commit_group;" ::: "memory")
#define CP_WAIT(n)  asm volatile("cp.async.wait_group %0;" :: "n"(n) : "memory")

__device__ __forceinline__ void ldsm4(uint32_t* r, uint32_t a) {
    asm volatile("ldmatrix.sync.aligned.m8n8.x4.shared.b16 {%0,%1,%2,%3}, [%4];"
                 : "=r"(r[0]), "=r"(r[1]), "=r"(r[2]), "=r"(r[3]) : "r"(a));
}
__device__ __forceinline__ void ldsm2(uint32_t* r, uint32_t a) {
    asm volatile("ldmatrix.sync.aligned.m8n8.x2.shared.b16 {%0,%1}, [%2];"
                 : "=r"(r[0]), "=r"(r[1]) : "r"(a));
}
__device__ __forceinline__ void ldsm2t(uint32_t* r, uint32_t a) {
    asm volatile("ldmatrix.sync.aligned.m8n8.x2.trans.shared.b16 {%0,%1}, [%2];"
                 : "=r"(r[0]), "=r"(r[1]) : "r"(a));
}
__device__ __forceinline__ void mma16816(float* c, const uint32_t* a, const uint32_t* b) {
    asm volatile("mma.sync.aligned.m16n8k16.row.col.f32.bf16.bf16.f32 "
                 "{%0,%1,%2,%3}, {%4,%5,%6,%7}, {%8,%9}, {%0,%1,%2,%3};"
                 : "+f"(c[0]), "+f"(c[1]), "+f"(c[2]), "+f"(c[3])
                 : "r"(a[0]), "r"(a[1]), "r"(a[2]), "r"(a[3]), "r"(b[0]), "r"(b[1]));
}

__device__ __forceinline__ uint32_t swz(int row, int colb) {
    uint32_t off = ((uint32_t)row << 7) + (uint32_t)colb;
    return off ^ (((uint32_t)row & 7u) << 4);
}
__device__ __forceinline__ uint32_t pack_bf2(bf16 a, bf16 b) {
    return (uint32_t)__bfloat16_as_ushort(b) << 16 | (uint32_t)__bfloat16_as_ushort(a);
}

// ---------------------------------------------------------------------------
// cp.async tile loader: bf16 gmem rows -> swizzled 128B smem rows
// ---------------------------------------------------------------------------
template<int ROWS>
__device__ __forceinline__ void cpa_tile(uint32_t dst, const bf16* __restrict__ src,
                                         int stride, int tid)
{
#pragma unroll
    for (int t = 0; t < ROWS * 8 / 256; t++) {
        int idx = tid + t * 256;
        int r = idx >> 3, u = idx & 7;
        cp16(dst + swz(r, u * 16), src + (size_t)r * stride + u * 8);
    }
}

// ---------------------------------------------------------------------------
// fp32 -> bf16 hi/lo split convert (grid-stride over float4)
// ---------------------------------------------------------------------------
__global__ __launch_bounds__(256)
void conv_hl(const float* __restrict__ src, bf16* __restrict__ h,
             bf16* __restrict__ l, int n4)
{
    int i = blockIdx.x * 256 + threadIdx.x;
    if (i >= n4) return;
    float4 v = ((const float4*)src)[i];
    bf16 h0 = __float2bfloat16(v.x), h1 = __float2bfloat16(v.y);
    bf16 h2 = __float2bfloat16(v.z), h3 = __float2bfloat16(v.w);
    bf16 l0 = __float2bfloat16(v.x - __bfloat162float(h0));
    bf16 l1 = __float2bfloat16(v.y - __bfloat162float(h1));
    bf16 l2 = __float2bfloat16(v.z - __bfloat162float(h2));
    bf16 l3 = __float2bfloat16(v.w - __bfloat162float(h3));
    uint2 hp; hp.x = pack_bf2(h0, h1); hp.y = pack_bf2(h2, h3);
    uint2 lp; lp.x = pack_bf2(l0, l1); lp.y = pack_bf2(l2, l3);
    ((uint2*)h)[i] = hp;
    ((uint2*)l)[i] = lp;
}

// ---------------------------------------------------------------------------
// Inner compute: one 64-wide K chunk, warp tile 32x32 (MF=2, NF=4)
// TB=true: B stored k-major ([k][n]) -> ldmatrix.trans
// ---------------------------------------------------------------------------
#define MF 2
#define NF 4

template<bool TB>
__device__ __forceinline__ void chunk_mma(float (*acc)[NF][4],
                                          uint32_t uAh, uint32_t uAl,
                                          uint32_t uBh, uint32_t uBl,
                                          int mw, int nw, int lane)
{
#pragma unroll
    for (int ks = 0; ks < 4; ks++) {
        uint32_t a_h[MF][4], a_l[MF][4], b_h[NF][2], b_l[NF][2];
        int acol = ks * 32 + ((lane >> 4) << 4);
#pragma unroll
        for (int mf = 0; mf < MF; mf++) {
            uint32_t sw = swz(mw + mf * 16 + (lane & 15), acol);
            ldsm4(a_h[mf], uAh + sw);
            ldsm4(a_l[mf], uAl + sw);
        }
#pragma unroll
        for (int nf = 0; nf < NF; nf++) {
            if (TB) {
                uint32_t sw = swz(ks * 16 + (lane & 15), (nw + nf * 8) * 2);
                ldsm2t(b_h[nf], uBh + sw);
                ldsm2t(b_l[nf], uBl + sw);
            } else {
                uint32_t sw = swz(nw + nf * 8 + (lane & 7), ks * 32 + ((lane & 8) << 1));
                ldsm2(b_h[nf], uBh + sw);
                ldsm2(b_l[nf], uBl + sw);
            }
        }
#pragma unroll
        for (int mf = 0; mf < MF; mf++)
#pragma unroll
            for (int nf = 0; nf < NF; nf++) {
                mma16816(acc[mf][nf], a_h[mf], b_h[nf]);
                mma16816(acc[mf][nf], a_h[mf], b_l[nf]);
                mma16816(acc[mf][nf], a_l[mf], b_h[nf]);
            }
    }
}

// ---------------------------------------------------------------------------
// Kernel: projection  C[8192x1024] = X @ W + bias  (block 128m x 64n)
// A: Xh/Xl [m][1024] bf16; B: Wh/Wl [k][1024] bf16 (trans-ldmatrix)
// OUT=0: fp32 [m][E] (d_out); OUT=1: bf16 hi/lo split-head [bh][l][64]
// smem: 2 bufs x (Ah 16K | Al 16K | Bh 8K | Bl 8K) = 96KB
// ---------------------------------------------------------------------------
#define PROJ_SMEM (2 * 49152)

template<int OUT>
__global__ __launch_bounds__(256, 2)
void proj_mma(const bf16* __restrict__ Xh, const bf16* __restrict__ Xl,
              const bf16* __restrict__ Wh, const bf16* __restrict__ Wl,
              const float* __restrict__ bias,
              float* __restrict__ out, bf16* __restrict__ Oh, bf16* __restrict__ Ol)
{
    extern __shared__ char sm[];
    const uint32_t sb = smem_u32(sm);
    const int tid = threadIdx.x;
    const int wid = tid >> 5, lane = tid & 31;
    const int mw = (wid >> 1) * 32;
    const int nw = (wid & 1) * 32;
    const int n0 = blockIdx.x * 64;
    const int m0 = blockIdx.y * 128;

    float acc[MF][NF][4];
#pragma unroll
    for (int i = 0; i < MF; i++)
#pragma unroll
        for (int j = 0; j < NF; j++)
#pragma unroll
            for (int kk = 0; kk < 4; kk++) acc[i][j][kk] = 0.0f;

    const bf16* Asrc_h = Xh + (size_t)m0 * E_;
    const bf16* Asrc_l = Xl + (size_t)m0 * E_;

    // prologue: chunk 0 into buf0
    cpa_tile<128>(sb,          Asrc_h, E_, tid);
    cpa_tile<128>(sb + 16384,  Asrc_l, E_, tid);
    cpa_tile<64>(sb + 32768,   Wh + n0, E_, tid);
    cpa_tile<64>(sb + 40960,   Wl + n0, E_, tid);
    CP_COMMIT();

    for (int c = 0; c < 16; c++) {
        const uint32_t bc = sb + (c & 1) * 49152;
        if (c < 15) {
            const uint32_t bn = sb + ((c + 1) & 1) * 49152;
            int k1 = (c + 1) * 64;
            cpa_tile<128>(bn,         Asrc_h + k1, E_, tid);
            cpa_tile<128>(bn + 16384, Asrc_l + k1, E_, tid);
            cpa_tile<64>(bn + 32768,  Wh + (size_t)k1 * E_ + n0, E_, tid);
            cpa_tile<64>(bn + 40960,  Wl + (size_t)k1 * E_ + n0, E_, tid);
            CP_COMMIT();
            CP_WAIT(1);
        } else {
            CP_WAIT(0);
        }
        __syncthreads();
        chunk_mma<true>(acc, bc, bc + 16384, bc + 32768, bc + 40960, mw, nw, lane);
        __syncthreads();
    }

    const int g = lane >> 2, tg = lane & 3;
#pragma unroll
    for (int mf = 0; mf < MF; mf++)
#pragma unroll
        for (int nf = 0; nf < NF; nf++) {
            int row = m0 + mw + mf * 16 + g;
            int col = n0 + nw + nf * 8 + tg * 2;
            float b0 = bias[col], b1 = bias[col + 1];
            float x0 = acc[mf][nf][0] + b0, y0 = acc[mf][nf][1] + b1;
            float x1 = acc[mf][nf][2] + b0, y1 = acc[mf][nf][3] + b1;
            if (OUT == 0) {
                float* dst = out + (size_t)row * E_ + col;
                *(float2*)dst            = make_float2(x0, y0);
                *(float2*)(dst + 8 * E_) = make_float2(x1, y1);
            } else {
                int b = row >> 11, l = row & (L_ - 1);
                int h = col >> 6, d = col & (D_ - 1);
                size_t i0 = (((size_t)(b * H_ + h)) * L_ + l) * D_ + d;
                size_t i1 = i0 + 8 * D_;
                bf16 hx0 = __float2bfloat16(x0), hy0 = __float2bfloat16(y0);
                bf16 hx1 = __float2bfloat16(x1), hy1 = __float2bfloat16(y1);
                bf16 lx0 = __float2bfloat16(x0 - __bfloat162float(hx0));
                bf16 ly0 = __float2bfloat16(y0 - __bfloat162float(hy0));
                bf16 lx1 = __float2bfloat16(x1 - __bfloat162float(hx1));
                bf16 ly1 = __float2bfloat16(y1 - __bfloat162float(hy1));
                *(uint32_t*)&Oh[i0] = pack_bf2(hx0, hy0);
                *(uint32_t*)&Ol[i0] = pack_bf2(lx0, ly0);
                *(uint32_t*)&Oh[i1] = pack_bf2(hx1, hy1);
                *(uint32_t*)&Ol[i1] = pack_bf2(lx1, ly1);
            }
        }
}

// ---------------------------------------------------------------------------
// Kernel: scores  (block 128q, loops 32 k-tiles; Q persistent, K double-buf)
// smem: Qh 16K | Ql 16K | 2 x (Kh 8K | Kl 8K) = 64KB
// ---------------------------------------------------------------------------
#define SCORES_SMEM (65536)

__global__ __launch_bounds__(256, 2)
void scores_mma(const bf16* __restrict__ Qh, const bf16* __restrict__ Ql,
                const bf16* __restrict__ Kh, const bf16* __restrict__ Kl,
                const int* __restrict__ mask, float* __restrict__ att)
{
    extern __shared__ char sm[];
    const uint32_t sb = smem_u32(sm);
    const int tid = threadIdx.x;
    const int wid = tid >> 5, lane = tid & 31;
    const int mw = (wid >> 1) * 32;
    const int nw = (wid & 1) * 32;
    const int q0 = blockIdx.x * 128;
    const int bh = blockIdx.y;
    const int b  = bh >> 4;
    const int g = lane >> 2, tg = lane & 3;

    const bf16* Kbh = Kh + (size_t)bh * L_ * D_;
    const bf16* Kbl = Kl + (size_t)bh * L_ * D_;
    const int*  mb  = mask + (size_t)b  * L_ * L_;
    float*      ab  = att  + (size_t)bh * L_ * L_;

    // prologue: persistent Q + K chunk 0
    cpa_tile<128>(sb,         Qh + ((size_t)bh * L_ + q0) * D_, D_, tid);
    cpa_tile<128>(sb + 16384, Ql + ((size_t)bh * L_ + q0) * D_, D_, tid);
    cpa_tile<64>(sb + 32768,  Kbh, D_, tid);
    cpa_tile<64>(sb + 40960,  Kbl, D_, tid);
    CP_COMMIT();

    for (int kt = 0; kt < 32; kt++) {
        const uint32_t kb = sb + 32768 + (kt & 1) * 16384;
        if (kt < 31) {
            const uint32_t kn = sb + 32768 + ((kt + 1) & 1) * 16384;
            cpa_tile<64>(kn,        Kbh + (size_t)(kt + 1) * 64 * D_, D_, tid);
            cpa_tile<64>(kn + 8192, Kbl + (size_t)(kt + 1) * 64 * D_, D_, tid);
            CP_COMMIT();
            CP_WAIT(1);
        } else {
            CP_WAIT(0);
        }
        __syncthreads();

        float acc[MF][NF][4];
#pragma unroll
        for (int i = 0; i < MF; i++)
#pragma unroll
            for (int j = 0; j < NF; j++)
#pragma unroll
                for (int kk = 0; kk < 4; kk++) acc[i][j][kk] = 0.0f;

        chunk_mma<false>(acc, sb, sb + 16384, kb, kb + 8192, mw, nw, lane);

        const int k0 = kt * 64;
#pragma unroll
        for (int mf = 0; mf < MF; mf++)
#pragma unroll
            for (int nf = 0; nf < NF; nf++) {
                int q = q0 + mw + mf * 16 + g;
                int k = k0 + nw + nf * 8 + tg * 2;
                size_t o1 = (size_t)q * L_ + k;
                size_t o2 = o1 + 8 * (size_t)L_;
                int2 m1 = *(const int2*)(mb + o1);
                int2 m2 = *(const int2*)(mb + o2);
                float2 v1, v2;
                v1.x = m1.x ? acc[mf][nf][0] * SCALE : NEG_INF;
                v1.y = m1.y ? acc[mf][nf][1] * SCALE : NEG_INF;
                v2.x = m2.x ? acc[mf][nf][2] * SCALE : NEG_INF;
                v2.y = m2.y ? acc[mf][nf][3] * SCALE : NEG_INF;
                *(float2*)(ab + o1) = v1;
                *(float2*)(ab + o2) = v2;
            }
        __syncthreads();
    }
}

// ---------------------------------------------------------------------------
// Kernel: softmax (row of 2048, one CTA per row)
// ---------------------------------------------------------------------------
__global__ __launch_bounds__(256)
void softmax_kernel(float* __restrict__ att)
{
    float* p = att + (size_t)blockIdx.x * L_;
    const int tid = threadIdx.x;
    float4 v0 = ((const float4*)p)[tid];
    float4 v1 = ((const float4*)p)[tid + 256];

    float m = fmaxf(fmaxf(fmaxf(v0.x, v0.y), fmaxf(v0.z, v0.w)),
                    fmaxf(fmaxf(v1.x, v1.y), fmaxf(v1.z, v1.w)));
    __shared__ float red[8];
#pragma unroll
    for (int o = 16; o > 0; o >>= 1)
        m = fmaxf(m, __shfl_xor_sync(0xffffffffu, m, o));
    if ((tid & 31) == 0) red[tid >> 5] = m;
    __syncthreads();
    float rmax = red[0];
#pragma unroll
    for (int w = 1; w < 8; w++) rmax = fmaxf(rmax, red[w]);
    __syncthreads();

    v0.x = __expf(v0.x - rmax); v0.y = __expf(v0.y - rmax);
    v0.z = __expf(v0.z - rmax); v0.w = __expf(v0.w - rmax);
    v1.x = __expf(v1.x - rmax); v1.y = __expf(v1.y - rmax);
    v1.z = __expf(v1.z - rmax); v1.w = __expf(v1.w - rmax);
    float s = v0.x + v0.y + v0.z + v0.w + v1.x + v1.y + v1.z + v1.w;
#pragma unroll
    for (int o = 16; o > 0; o >>= 1)
        s += __shfl_xor_sync(0xffffffffu, s, o);
    if ((tid & 31) == 0) red[tid >> 5] = s;
    __syncthreads();
    float rsum = 0.0f;
#pragma unroll
    for (int w = 0; w < 8; w++) rsum += red[w];
    float inv = 1.0f / rsum;

    v0.x *= inv; v0.y *= inv; v0.z *= inv; v0.w *= inv;
    v1.x *= inv; v1.y *= inv; v1.z *= inv; v1.w *= inv;
    ((float4*)p)[tid]       = v0;
    ((float4*)p)[tid + 256] = v1;
}

// ---------------------------------------------------------------------------
// Kernel: AV  ctx = P @ V  (block 128m x 64d, 32 chunks)
// A: att fp32 inline-converted (reg prefetch one chunk ahead); B: Vh/Vl cp.async
// smem: Ath 16K | Atl 16K | 2 x (Bh 8K | Bl 8K) = 64KB
// Output: ctx bf16 hi/lo [m][E]
// ---------------------------------------------------------------------------
#define AV_SMEM (65536)

__global__ __launch_bounds__(256, 2)
void av_mma(const float* __restrict__ att,
            const bf16* __restrict__ Vh, const bf16* __restrict__ Vl,
            bf16* __restrict__ Ch, bf16* __restrict__ Cl)
{
    extern __shared__ char sm[];
    char* Ath = sm;
    char* Atl = sm + 16384;
    const uint32_t sb = smem_u32(sm);
    const int tid = threadIdx.x;
    const int wid = tid >> 5, lane = tid & 31;
    const int mw = (wid >> 1) * 32;
    const int nw = (wid & 1) * 32;
    const int m0 = blockIdx.x * 128;
    const int bh = blockIdx.y;
    const int b  = bh >> 4, h = bh & 15;

    const float* Ab  = att + (size_t)bh * L_ * L_ + (size_t)m0 * L_;
    const bf16*  Vbh = Vh + (size_t)bh * L_ * D_;
    const bf16*  Vbl = Vl + (size_t)bh * L_ * D_;

    float acc[MF][NF][4];
#pragma unroll
    for (int i = 0; i < MF; i++)
#pragma unroll
        for (int j = 0; j < NF; j++)
#pragma unroll
            for (int kk = 0; kk < 4; kk++) acc[i][j][kk] = 0.0f;

    float4 ar[8];
    // prologue: A chunk 0 -> regs -> smem; B chunk 0 cp.async
#pragma unroll
    for (int t = 0; t < 8; t++) {
        int idx = tid + t * 256;
        int r = idx >> 4, q = idx & 15;
        ar[t] = *(const float4*)(Ab + (size_t)r * L_ + q * 4);
    }
#pragma unroll
    for (int t = 0; t < 8; t++) {
        int idx = tid + t * 256;
        int r = idx >> 4, q = idx & 15;
        bf16 h0 = __float2bfloat16(ar[t].x), h1 = __float2bfloat16(ar[t].y);
        bf16 h2 = __float2bfloat16(ar[t].z), h3 = __float2bfloat16(ar[t].w);
        bf16 l0 = __float2bfloat16(ar[t].x - __bfloat162float(h0));
        bf16 l1 = __float2bfloat16(ar[t].y - __bfloat162float(h1));
        bf16 l2 = __float2bfloat16(ar[t].z - __bfloat162float(h2));
        bf16 l3 = __float2bfloat16(ar[t].w - __bfloat162float(h3));
        uint32_t sw = swz(r, q * 8);
        uint2 hp; hp.x = pack_bf2(h0, h1); hp.y = pack_bf2(h2, h3);
        uint2 lp; lp.x = pack_bf2(l0, l1); lp.y = pack_bf2(l2, l3);
        *(uint2*)(Ath + sw) = hp;
        *(uint2*)(Atl + sw) = lp;
    }
    cpa_tile<64>(sb + 32768, Vbh, D_, tid);
    cpa_tile<64>(sb + 40960, Vbl, D_, tid);
    CP_COMMIT();

    for (int c = 0; c < 32; c++) {
        const uint32_t vb = sb + 32768 + (c & 1) * 16384;
        if (c < 31) {
            // prefetch next A chunk into regs (rides under the mma below)
#pragma unroll
            for (int t = 0; t < 8; t++) {
                int idx = tid + t * 256;
                int r = idx >> 4, q = idx & 15;
                ar[t] = *(const float4*)(Ab + (size_t)r * L_ + (c + 1) * 64 + q * 4);
            }
            const uint32_t vn = sb + 32768 + ((c + 1) & 1) * 16384;
            cpa_tile<64>(vn,        Vbh + (size_t)(c + 1) * 64 * D_, D_, tid);
            cpa_tile<64>(vn + 8192, Vbl + (size_t)(c + 1) * 64 * D_, D_, tid);
            CP_COMMIT();
            CP_WAIT(1);
        } else {
            CP_WAIT(0);
        }
        __syncthreads();
        chunk_mma<true>(acc, sb, sb + 16384, vb, vb + 8192, mw, nw, lane);
        __syncthreads();
        if (c < 31) {
#pragma unroll
            for (int t = 0; t < 8; t++) {
                int idx = tid + t * 256;
                int r = idx >> 4, q = idx & 15;
                bf16 h0 = __float2bfloat16(ar[t].x), h1 = __float2bfloat16(ar[t].y);
                bf16 h2 = __float2bfloat16(ar[t].z), h3 = __float2bfloat16(ar[t].w);
                bf16 l0 = __float2bfloat16(ar[t].x - __bfloat162float(h0));
                bf16 l1 = __float2bfloat16(ar[t].y - __bfloat162float(h1));
                bf16 l2 = __float2bfloat16(ar[t].z - __bfloat162float(h2));
                bf16 l3 = __float2bfloat16(ar[t].w - __bfloat162float(h3));
                uint32_t sw = swz(r, q * 8);
                uint2 hp; hp.x = pack_bf2(h0, h1); hp.y = pack_bf2(h2, h3);
                uint2 lp; lp.x = pack_bf2(l0, l1); lp.y = pack_bf2(l2, l3);
                *(uint2*)(Ath + sw) = hp;
                *(uint2*)(Atl + sw) = lp;
            }
        }
    }

    const int g = lane >> 2, tg = lane & 3;
#pragma unroll
    for (int mf = 0; mf < MF; mf++)
#pragma unroll
        for (int nf = 0; nf < NF; nf++) {
            int m   = m0 + mw + mf * 16 + g;
            int col = nw + nf * 8 + tg * 2;
            size_t i0 = ((size_t)b * L_ + m) * E_ + h * D_ + col;
            size_t i1 = i0 + 8 * E_;
            float x0 = acc[mf][nf][0], y0 = acc[mf][nf][1];
            float x1 = acc[mf][nf][2], y1 = acc[mf][nf][3];
            bf16 hx0 = __float2bfloat16(x0), hy0 = __float2bfloat16(y0);
            bf16 hx1 = __float2bfloat16(x1), hy1 = __float2bfloat16(y1);
            bf16 lx0 = __float2bfloat16(x0 - __bfloat162float(hx0));
            bf16 ly0 = __float2bfloat16(y0 - __bfloat162float(hy0));
            bf16 lx1 = __float2bfloat16(x1 - __bfloat162float(hx1));
            bf16 ly1 = __float2bfloat16(y1 - __bfloat162float(hy1));
            *(uint32_t*)&Ch[i0] = pack_bf2(hx0, hy0);
            *(uint32_t*)&Cl[i0] = pack_bf2(lx0, ly0);
            *(uint32_t*)&Ch[i1] = pack_bf2(hx1, hy1);
            *(uint32_t*)&Cl[i1] = pack_bf2(lx1, ly1);
        }
}

// ---------------------------------------------------------------------------
// Launch
// ---------------------------------------------------------------------------
extern "C" void kernel_launch(void* const* d_in, const int* in_sizes, int n_in,
                              void* d_out, int out_size)
{
    const float* iq = (const float*)d_in[0];
    const float* ik = (const float*)d_in[1];
    const float* iv = (const float*)d_in[2];
    const int*   mk = (const int*)  d_in[3];
    const float* Wq = (const float*)d_in[4];
    const float* bq = (const float*)d_in[5];
    const float* Wk = (const float*)d_in[6];
    const float* bk = (const float*)d_in[7];
    const float* Wv = (const float*)d_in[8];
    const float* bv = (const float*)d_in[9];
    const float* Wo = (const float*)d_in[10];
    const float* bo = (const float*)d_in[11];

    float* o_out = (float*)d_out;
    const long long o_elems   = (long long)MTOK * E_;
    const long long att_elems = (long long)B_ * H_ * L_ * L_;

    bf16 *Qh, *Ql, *Kh, *Kl, *Vh, *Vl, *Xh, *Xl, *Wh, *Wl, *Ch, *Cl;
    float* Ap;
    cudaGetSymbolAddress((void**)&Qh, g_Qh); cudaGetSymbolAddress((void**)&Ql, g_Ql);
    cudaGetSymbolAddress((void**)&Kh, g_Kh); cudaGetSymbolAddress((void**)&Kl, g_Kl);
    cudaGetSymbolAddress((void**)&Vh, g_Vh); cudaGetSymbolAddress((void**)&Vl, g_Vl);
    cudaGetSymbolAddress((void**)&Xh, g_Xh); cudaGetSymbolAddress((void**)&Xl, g_Xl);
    cudaGetSymbolAddress((void**)&Wh, g_Wh); cudaGetSymbolAddress((void**)&Wl, g_Wl);
    cudaGetSymbolAddress((void**)&Ch, g_Ch); cudaGetSymbolAddress((void**)&Cl, g_Cl);
    cudaGetSymbolAddress((void**)&Ap, g_att_fallback);

    float* att = ((long long)out_size >= o_elems + att_elems)
                     ? (o_out + o_elems) : Ap;

    cudaFuncSetAttribute(proj_mma<1>, cudaFuncAttributeMaxDynamicSharedMemorySize, PROJ_SMEM);
    cudaFuncSetAttribute(proj_mma<0>, cudaFuncAttributeMaxDynamicSharedMemorySize, PROJ_SMEM);
    cudaFuncSetAttribute(scores_mma,  cudaFuncAttributeMaxDynamicSharedMemorySize, SCORES_SMEM);
    cudaFuncSetAttribute(av_mma,      cudaFuncAttributeMaxDynamicSharedMemorySize, AV_SMEM);

    const int nx4 = MTOK * E_ / 4;   // X float4 count
    const int nw4 = E_ * E_ / 4;     // W float4 count
    dim3 gp(E_ / 64, MTOK / 128);    // (16, 64)

    // Q
    conv_hl<<<(nx4 + 255) / 256, 256>>>(iq, Xh, Xl, nx4);
    conv_hl<<<(nw4 + 255) / 256, 256>>>(Wq, Wh, Wl, nw4);
    proj_mma<1><<<gp, 256, PROJ_SMEM>>>(Xh, Xl, Wh, Wl, bq, nullptr, Qh, Ql);
    // K
    conv_hl<<<(nx4 + 255) / 256, 256>>>(ik, Xh, Xl, nx4);
    conv_hl<<<(nw4 + 255) / 256, 256>>>(Wk, Wh, Wl, nw4);
    proj_mma<1><<<gp, 256, PROJ_SMEM>>>(Xh, Xl, Wh, Wl, bk, nullptr, Kh, Kl);
    // V
    conv_hl<<<(nx4 + 255) / 256, 256>>>(iv, Xh, Xl, nx4);
    conv_hl<<<(nw4 + 255) / 256, 256>>>(Wv, Wh, Wl, nw4);
    proj_mma<1><<<gp, 256, PROJ_SMEM>>>(Xh, Xl, Wh, Wl, bv, nullptr, Vh, Vl);

    // scores + softmax
    dim3 gs(L_ / 128, B_ * H_);                 // (16, 64)
    scores_mma<<<gs, 256, SCORES_SMEM>>>(Qh, Ql, Kh, Kl, mk, att);
    softmax_kernel<<<B_ * H_ * L_, 256>>>(att);

    // AV
    av_mma<<<gs, 256, AV_SMEM>>>(att, Vh, Vl, Ch, Cl);

    // output projection
    conv_hl<<<(nw4 + 255) / 256, 256>>>(Wo, Wh, Wl, nw4);
    proj_mma<0><<<gp, 256, PROJ_SMEM>>>(Ch, Cl, Wh, Wl, bo, o_out, nullptr, nullptr);
}

// round 6
// speedup vs baseline: 2.7993x; 1.2272x over previous
#include <cuda_runtime.h>
#include <cuda_bf16.h>
#include <cstdint>

// Problem constants
#define B_   4
#define L_   2048
#define E_   1024
#define H_   16
#define D_   64
#define MTOK (B_*L_)
#define NEG_INF (-1.0e9f)
#define SCALE   0.125f

typedef __nv_bfloat16 bf16;

// ---------------------------------------------------------------------------
// Static device scratch
// ---------------------------------------------------------------------------
__device__ bf16 g_Qh[(size_t)MTOK * E_], g_Ql[(size_t)MTOK * E_];   // [bh][l][64]
__device__ bf16 g_Kh[(size_t)MTOK * E_], g_Kl[(size_t)MTOK * E_];
__device__ bf16 g_Vh[(size_t)MTOK * E_], g_Vl[(size_t)MTOK * E_];
__device__ bf16 g_Xh[(size_t)MTOK * E_], g_Xl[(size_t)MTOK * E_];   // input staging
__device__ bf16 g_Wh[(size_t)E_ * E_],   g_Wl[(size_t)E_ * E_];     // weight staging
__device__ bf16 g_Ch[(size_t)MTOK * E_], g_Cl[(size_t)MTOK * E_];   // ctx
__device__ uint32_t g_mbits[(size_t)B_ * L_ * (L_ / 32)];           // 2 MB bitmask
__device__ float g_sm[(size_t)B_ * H_ * L_];                        // row max
__device__ float g_sl[(size_t)B_ * H_ * L_];                        // row sum
__device__ float g_att_fallback[(size_t)B_ * H_ * L_ * L_];

// ---------------------------------------------------------------------------
// PTX helpers
// ---------------------------------------------------------------------------
__device__ __forceinline__ uint32_t smem_u32(const void* p) {
    uint32_t a;
    asm("{ .reg .u64 t; cvta.to.shared.u64 t, %1; cvt.u32.u64 %0, t; }"
        : "=r"(a) : "l"(p));
    return a;
}
__device__ __forceinline__ void cp16(uint32_t dst, const void* src) {
    asm volatile("cp.async.cg.shared.global [%0], [%1], 16;" :: "r"(dst), "l"(src));
}
#define CP_COMMIT() asm volatile("cp.async.commit_group;" ::: "memory")
#define CP_WAIT(n)  asm volatile("cp.async.wait_group %0;" :: "n"(n) : "memory")

__device__ __forceinline__ void ldsm4(uint32_t* r, uint32_t a) {
    asm volatile("ldmatrix.sync.aligned.m8n8.x4.shared.b16 {%0,%1,%2,%3}, [%4];"
                 : "=r"(r[0]), "=r"(r[1]), "=r"(r[2]), "=r"(r[3]) : "r"(a));
}
__device__ __forceinline__ void ldsm2(uint32_t* r, uint32_t a) {
    asm volatile("ldmatrix.sync.aligned.m8n8.x2.shared.b16 {%0,%1}, [%2];"
                 : "=r"(r[0]), "=r"(r[1]) : "r"(a));
}
__device__ __forceinline__ void ldsm2t(uint32_t* r, uint32_t a) {
    asm volatile("ldmatrix.sync.aligned.m8n8.x2.trans.shared.b16 {%0,%1}, [%2];"
                 : "=r"(r[0]), "=r"(r[1]) : "r"(a));
}
__device__ __forceinline__ void mma16816(float* c, const uint32_t* a, const uint32_t* b) {
    asm volatile("mma.sync.aligned.m16n8k16.row.col.f32.bf16.bf16.f32 "
                 "{%0,%1,%2,%3}, {%4,%5,%6,%7}, {%8,%9}, {%0,%1,%2,%3};"
                 : "+f"(c[0]), "+f"(c[1]), "+f"(c[2]), "+f"(c[3])
                 : "r"(a[0]), "r"(a[1]), "r"(a[2]), "r"(a[3]), "r"(b[0]), "r"(b[1]));
}

__device__ __forceinline__ uint32_t swz(int row, int colb) {
    uint32_t off = ((uint32_t)row << 7) + (uint32_t)colb;
    return off ^ (((uint32_t)row & 7u) << 4);
}
__device__ __forceinline__ uint32_t pack_bf2(bf16 a, bf16 b) {
    return (uint32_t)__bfloat16_as_ushort(b) << 16 | (uint32_t)__bfloat16_as_ushort(a);
}

// ---------------------------------------------------------------------------
// cp.async tile loader
// ---------------------------------------------------------------------------
template<int ROWS>
__device__ __forceinline__ void cpa_tile(uint32_t dst, const bf16* __restrict__ src,
                                         int stride, int tid)
{
#pragma unroll
    for (int t = 0; t < ROWS * 8 / 256; t++) {
        int idx = tid + t * 256;
        int r = idx >> 3, u = idx & 7;
        cp16(dst + swz(r, u * 16), src + (size_t)r * stride + u * 8);
    }
}

// ---------------------------------------------------------------------------
// fp32 -> bf16 hi/lo split convert
// ---------------------------------------------------------------------------
__global__ __launch_bounds__(256)
void conv_hl(const float* __restrict__ src, bf16* __restrict__ h,
             bf16* __restrict__ l, int n4)
{
    int i = blockIdx.x * 256 + threadIdx.x;
    if (i >= n4) return;
    float4 v = ((const float4*)src)[i];
    bf16 h0 = __float2bfloat16(v.x), h1 = __float2bfloat16(v.y);
    bf16 h2 = __float2bfloat16(v.z), h3 = __float2bfloat16(v.w);
    bf16 l0 = __float2bfloat16(v.x - __bfloat162float(h0));
    bf16 l1 = __float2bfloat16(v.y - __bfloat162float(h1));
    bf16 l2 = __float2bfloat16(v.z - __bfloat162float(h2));
    bf16 l3 = __float2bfloat16(v.w - __bfloat162float(h3));
    uint2 hp; hp.x = pack_bf2(h0, h1); hp.y = pack_bf2(h2, h3);
    uint2 lp; lp.x = pack_bf2(l0, l1); lp.y = pack_bf2(l2, l3);
    ((uint2*)h)[i] = hp;
    ((uint2*)l)[i] = lp;
}

// ---------------------------------------------------------------------------
// mask int32 -> bitmask (warp ballot; fully coalesced)
// ---------------------------------------------------------------------------
__global__ __launch_bounds__(256)
void mask_bits(const int* __restrict__ mask, uint32_t* __restrict__ bits)
{
    int i = blockIdx.x * 256 + threadIdx.x;
    uint32_t bal = __ballot_sync(0xffffffffu, mask[i] != 0);
    if ((threadIdx.x & 31) == 0) bits[i >> 5] = bal;
}

// ---------------------------------------------------------------------------
// Inner compute: one 64-wide K chunk, warp tile 32x32 (MF=2, NF=4)
// ---------------------------------------------------------------------------
#define MF 2
#define NF 4

template<bool TB>
__device__ __forceinline__ void chunk_mma(float (*acc)[NF][4],
                                          uint32_t uAh, uint32_t uAl,
                                          uint32_t uBh, uint32_t uBl,
                                          int mw, int nw, int lane)
{
#pragma unroll
    for (int ks = 0; ks < 4; ks++) {
        uint32_t a_h[MF][4], a_l[MF][4], b_h[NF][2], b_l[NF][2];
        int acol = ks * 32 + ((lane >> 4) << 4);
#pragma unroll
        for (int mf = 0; mf < MF; mf++) {
            uint32_t sw = swz(mw + mf * 16 + (lane & 15), acol);
            ldsm4(a_h[mf], uAh + sw);
            ldsm4(a_l[mf], uAl + sw);
        }
#pragma unroll
        for (int nf = 0; nf < NF; nf++) {
            if (TB) {
                uint32_t sw = swz(ks * 16 + (lane & 15), (nw + nf * 8) * 2);
                ldsm2t(b_h[nf], uBh + sw);
                ldsm2t(b_l[nf], uBl + sw);
            } else {
                uint32_t sw = swz(nw + nf * 8 + (lane & 7), ks * 32 + ((lane & 8) << 1));
                ldsm2(b_h[nf], uBh + sw);
                ldsm2(b_l[nf], uBl + sw);
            }
        }
#pragma unroll
        for (int mf = 0; mf < MF; mf++)
#pragma unroll
            for (int nf = 0; nf < NF; nf++) {
                mma16816(acc[mf][nf], a_h[mf], b_h[nf]);
                mma16816(acc[mf][nf], a_h[mf], b_l[nf]);
                mma16816(acc[mf][nf], a_l[mf], b_h[nf]);
            }
    }
}

// ---------------------------------------------------------------------------
// Kernel: projection  (block 128m x 64n); unchanged from R5
// ---------------------------------------------------------------------------
#define PROJ_SMEM (2 * 49152)

template<int OUT>
__global__ __launch_bounds__(256, 2)
void proj_mma(const bf16* __restrict__ Xh, const bf16* __restrict__ Xl,
              const bf16* __restrict__ Wh, const bf16* __restrict__ Wl,
              const float* __restrict__ bias,
              float* __restrict__ out, bf16* __restrict__ Oh, bf16* __restrict__ Ol)
{
    extern __shared__ char sm[];
    const uint32_t sb = smem_u32(sm);
    const int tid = threadIdx.x;
    const int wid = tid >> 5, lane = tid & 31;
    const int mw = (wid >> 1) * 32;
    const int nw = (wid & 1) * 32;
    const int n0 = blockIdx.x * 64;
    const int m0 = blockIdx.y * 128;

    float acc[MF][NF][4];
#pragma unroll
    for (int i = 0; i < MF; i++)
#pragma unroll
        for (int j = 0; j < NF; j++)
#pragma unroll
            for (int kk = 0; kk < 4; kk++) acc[i][j][kk] = 0.0f;

    const bf16* Asrc_h = Xh + (size_t)m0 * E_;
    const bf16* Asrc_l = Xl + (size_t)m0 * E_;

    cpa_tile<128>(sb,          Asrc_h, E_, tid);
    cpa_tile<128>(sb + 16384,  Asrc_l, E_, tid);
    cpa_tile<64>(sb + 32768,   Wh + n0, E_, tid);
    cpa_tile<64>(sb + 40960,   Wl + n0, E_, tid);
    CP_COMMIT();

    for (int c = 0; c < 16; c++) {
        const uint32_t bc = sb + (c & 1) * 49152;
        if (c < 15) {
            const uint32_t bn = sb + ((c + 1) & 1) * 49152;
            int k1 = (c + 1) * 64;
            cpa_tile<128>(bn,         Asrc_h + k1, E_, tid);
            cpa_tile<128>(bn + 16384, Asrc_l + k1, E_, tid);
            cpa_tile<64>(bn + 32768,  Wh + (size_t)k1 * E_ + n0, E_, tid);
            cpa_tile<64>(bn + 40960,  Wl + (size_t)k1 * E_ + n0, E_, tid);
            CP_COMMIT();
            CP_WAIT(1);
        } else {
            CP_WAIT(0);
        }
        __syncthreads();
        chunk_mma<true>(acc, bc, bc + 16384, bc + 32768, bc + 40960, mw, nw, lane);
        __syncthreads();
    }

    const int g = lane >> 2, tg = lane & 3;
#pragma unroll
    for (int mf = 0; mf < MF; mf++)
#pragma unroll
        for (int nf = 0; nf < NF; nf++) {
            int row = m0 + mw + mf * 16 + g;
            int col = n0 + nw + nf * 8 + tg * 2;
            float b0 = bias[col], b1 = bias[col + 1];
            float x0 = acc[mf][nf][0] + b0, y0 = acc[mf][nf][1] + b1;
            float x1 = acc[mf][nf][2] + b0, y1 = acc[mf][nf][3] + b1;
            if (OUT == 0) {
                float* dst = out + (size_t)row * E_ + col;
                *(float2*)dst            = make_float2(x0, y0);
                *(float2*)(dst + 8 * E_) = make_float2(x1, y1);
            } else {
                int b = row >> 11, l = row & (L_ - 1);
                int h = col >> 6, d = col & (D_ - 1);
                size_t i0 = (((size_t)(b * H_ + h)) * L_ + l) * D_ + d;
                size_t i1 = i0 + 8 * D_;
                bf16 hx0 = __float2bfloat16(x0), hy0 = __float2bfloat16(y0);
                bf16 hx1 = __float2bfloat16(x1), hy1 = __float2bfloat16(y1);
                bf16 lx0 = __float2bfloat16(x0 - __bfloat162float(hx0));
                bf16 ly0 = __float2bfloat16(y0 - __bfloat162float(hy0));
                bf16 lx1 = __float2bfloat16(x1 - __bfloat162float(hx1));
                bf16 ly1 = __float2bfloat16(y1 - __bfloat162float(hy1));
                *(uint32_t*)&Oh[i0] = pack_bf2(hx0, hy0);
                *(uint32_t*)&Ol[i0] = pack_bf2(lx0, ly0);
                *(uint32_t*)&Oh[i1] = pack_bf2(hx1, hy1);
                *(uint32_t*)&Ol[i1] = pack_bf2(lx1, ly1);
            }
        }
}

// ---------------------------------------------------------------------------
// Kernel: scores + online softmax stats
// Writes raw masked scaled scores to att; per-row (max, sumexp) to gm/gl.
// smem: Qh 16K | Ql 16K | 2 x (Kh 8K | Kl 8K) = 64KB dynamic
// ---------------------------------------------------------------------------
#define SCORES_SMEM (65536)

__global__ __launch_bounds__(256, 2)
void scores_mma(const bf16* __restrict__ Qh, const bf16* __restrict__ Ql,
                const bf16* __restrict__ Kh, const bf16* __restrict__ Kl,
                const uint32_t* __restrict__ mbits, float* __restrict__ att,
                float* __restrict__ gm, float* __restrict__ gl)
{
    extern __shared__ char sm[];
    __shared__ uint32_t sBits[256];          // 128 rows x 2 words per k-tile
    __shared__ float2  sRed[128][2];         // per-row (m,s) per n-warp
    const uint32_t sb = smem_u32(sm);
    const int tid = threadIdx.x;
    const int wid = tid >> 5, lane = tid & 31;
    const int mw = (wid >> 1) * 32;
    const int nw = (wid & 1) * 32;
    const int q0 = blockIdx.x * 128;
    const int bh = blockIdx.y;
    const int b  = bh >> 4;
    const int g = lane >> 2, tg = lane & 3;

    const bf16* Kbh = Kh + (size_t)bh * L_ * D_;
    const bf16* Kbl = Kl + (size_t)bh * L_ * D_;
    const uint32_t* bb = mbits + ((size_t)b * L_ + q0) * (L_ / 32);
    float* ab = att + (size_t)bh * L_ * L_;

    cpa_tile<128>(sb,         Qh + ((size_t)bh * L_ + q0) * D_, D_, tid);
    cpa_tile<128>(sb + 16384, Ql + ((size_t)bh * L_ + q0) * D_, D_, tid);
    cpa_tile<64>(sb + 32768,  Kbh, D_, tid);
    cpa_tile<64>(sb + 40960,  Kbl, D_, tid);
    CP_COMMIT();

    // online stats: rows (mf, g) and (mf, g+8)
    float rm[MF][2], rs[MF][2];
#pragma unroll
    for (int i = 0; i < MF; i++) {
        rm[i][0] = rm[i][1] = -3.0e38f;
        rs[i][0] = rs[i][1] = 0.0f;
    }

    for (int kt = 0; kt < 32; kt++) {
        // stage this tile's mask words: 128 rows x 2 words
        {
            int r = tid >> 1, w = tid & 1;
            sBits[tid] = bb[(size_t)r * (L_ / 32) + kt * 2 + w];
        }
        const uint32_t kb = sb + 32768 + (kt & 1) * 16384;
        if (kt < 31) {
            const uint32_t kn = sb + 32768 + ((kt + 1) & 1) * 16384;
            cpa_tile<64>(kn,        Kbh + (size_t)(kt + 1) * 64 * D_, D_, tid);
            cpa_tile<64>(kn + 8192, Kbl + (size_t)(kt + 1) * 64 * D_, D_, tid);
            CP_COMMIT();
            CP_WAIT(1);
        } else {
            CP_WAIT(0);
        }
        __syncthreads();

        float acc[MF][NF][4];
#pragma unroll
        for (int i = 0; i < MF; i++)
#pragma unroll
            for (int j = 0; j < NF; j++)
#pragma unroll
                for (int kk = 0; kk < 4; kk++) acc[i][j][kk] = 0.0f;

        chunk_mma<false>(acc, sb, sb + 16384, kb, kb + 8192, mw, nw, lane);

        const int k0 = kt * 64;
#pragma unroll
        for (int mf = 0; mf < MF; mf++) {
            const int r0 = mw + mf * 16 + g;      // local row
            const int r1 = r0 + 8;
#pragma unroll
            for (int nf = 0; nf < NF; nf++) {
                int knw = nw + nf * 8 + tg * 2;   // local col
                int wsel = knw >> 5;
                uint32_t w0 = sBits[r0 * 2 + wsel];
                uint32_t w1 = sBits[r1 * 2 + wsel];
                int bp = knw & 31;
                float2 v1, v2;
                v1.x = (w0 >> bp) & 1u       ? acc[mf][nf][0] * SCALE : NEG_INF;
                v1.y = (w0 >> (bp + 1)) & 1u ? acc[mf][nf][1] * SCALE : NEG_INF;
                v2.x = (w1 >> bp) & 1u       ? acc[mf][nf][2] * SCALE : NEG_INF;
                v2.y = (w1 >> (bp + 1)) & 1u ? acc[mf][nf][3] * SCALE : NEG_INF;
                // online softmax stats
                float nm0 = fmaxf(rm[mf][0], fmaxf(v1.x, v1.y));
                rs[mf][0] = rs[mf][0] * __expf(rm[mf][0] - nm0)
                          + __expf(v1.x - nm0) + __expf(v1.y - nm0);
                rm[mf][0] = nm0;
                float nm1 = fmaxf(rm[mf][1], fmaxf(v2.x, v2.y));
                rs[mf][1] = rs[mf][1] * __expf(rm[mf][1] - nm1)
                          + __expf(v2.x - nm1) + __expf(v2.y - nm1);
                rm[mf][1] = nm1;
                size_t o1 = (size_t)(q0 + r0) * L_ + k0 + knw;
                size_t o2 = (size_t)(q0 + r1) * L_ + k0 + knw;
                *(float2*)(ab + o1) = v1;
                *(float2*)(ab + o2) = v2;
            }
        }
        __syncthreads();
    }

    // reduce stats over tg lanes (cols) then over the 2 n-warps
#pragma unroll
    for (int mf = 0; mf < MF; mf++)
#pragma unroll
        for (int rr = 0; rr < 2; rr++) {
            float m = rm[mf][rr], s = rs[mf][rr];
#pragma unroll
            for (int off = 1; off <= 2; off <<= 1) {
                float om = __shfl_xor_sync(0xffffffffu, m, off);
                float os = __shfl_xor_sync(0xffffffffu, s, off);
                float nm = fmaxf(m, om);
                s = s * __expf(m - nm) + os * __expf(om - nm);
                m = nm;
            }
            if (tg == 0) {
                int row = mw + mf * 16 + g + rr * 8;
                sRed[row][wid & 1] = make_float2(m, s);
            }
        }
    __syncthreads();
    if (tid < 128) {
        float2 a = sRed[tid][0], c = sRed[tid][1];
        float nm = fmaxf(a.x, c.x);
        float s = a.y * __expf(a.x - nm) + c.y * __expf(c.x - nm);
        gm[(size_t)bh * L_ + q0 + tid] = nm;
        gl[(size_t)bh * L_ + q0 + tid] = s;
    }
}

// ---------------------------------------------------------------------------
// Kernel: AV + softmax normalization
// Reads raw scores; p = exp(s-m)*inv_l; writes normalized att in place;
// MMAs p (bf16 hi/lo) against V; writes ctx bf16 hi/lo.
// smem: Ath 16K | Atl 16K | 2 x (Bh 8K | Bl 8K) = 64KB dynamic
// ---------------------------------------------------------------------------
#define AV_SMEM (65536)

__global__ __launch_bounds__(256, 2)
void av_mma(float* __restrict__ att,
            const bf16* __restrict__ Vh, const bf16* __restrict__ Vl,
            const float* __restrict__ gm, const float* __restrict__ gl,
            bf16* __restrict__ Ch, bf16* __restrict__ Cl)
{
    extern __shared__ char sm[];
    char* Ath = sm;
    char* Atl = sm + 16384;
    __shared__ float sM[128], sI[128];
    const uint32_t sb = smem_u32(sm);
    const int tid = threadIdx.x;
    const int wid = tid >> 5, lane = tid & 31;
    const int mw = (wid >> 1) * 32;
    const int nw = (wid & 1) * 32;
    const int m0 = blockIdx.x * 128;
    const int bh = blockIdx.y;
    const int b  = bh >> 4, h = bh & 15;

    float* Ab = att + (size_t)bh * L_ * L_ + (size_t)m0 * L_;
    const bf16* Vbh = Vh + (size_t)bh * L_ * D_;
    const bf16* Vbl = Vl + (size_t)bh * L_ * D_;

    if (tid < 128) {
        sM[tid] = gm[(size_t)bh * L_ + m0 + tid];
        sI[tid] = 1.0f / gl[(size_t)bh * L_ + m0 + tid];
    }

    float acc[MF][NF][4];
#pragma unroll
    for (int i = 0; i < MF; i++)
#pragma unroll
        for (int j = 0; j < NF; j++)
#pragma unroll
            for (int kk = 0; kk < 4; kk++) acc[i][j][kk] = 0.0f;

    float4 ar[8];
#pragma unroll
    for (int t = 0; t < 8; t++) {
        int idx = tid + t * 256;
        int r = idx >> 4, q = idx & 15;
        ar[t] = *(const float4*)(Ab + (size_t)r * L_ + q * 4);
    }
    cpa_tile<64>(sb + 32768, Vbh, D_, tid);
    cpa_tile<64>(sb + 40960, Vbl, D_, tid);
    CP_COMMIT();
    __syncthreads();    // sM/sI visible

    // convert chunk 0: normalize, write back, split to smem
#pragma unroll
    for (int t = 0; t < 8; t++) {
        int idx = tid + t * 256;
        int r = idx >> 4, q = idx & 15;
        float4 p;
        p.x = __expf(ar[t].x - sM[r]) * sI[r];
        p.y = __expf(ar[t].y - sM[r]) * sI[r];
        p.z = __expf(ar[t].z - sM[r]) * sI[r];
        p.w = __expf(ar[t].w - sM[r]) * sI[r];
        *(float4*)(Ab + (size_t)r * L_ + q * 4) = p;
        bf16 h0 = __float2bfloat16(p.x), h1 = __float2bfloat16(p.y);
        bf16 h2 = __float2bfloat16(p.z), h3 = __float2bfloat16(p.w);
        bf16 l0 = __float2bfloat16(p.x - __bfloat162float(h0));
        bf16 l1 = __float2bfloat16(p.y - __bfloat162float(h1));
        bf16 l2 = __float2bfloat16(p.z - __bfloat162float(h2));
        bf16 l3 = __float2bfloat16(p.w - __bfloat162float(h3));
        uint32_t sw = swz(r, q * 8);
        uint2 hp; hp.x = pack_bf2(h0, h1); hp.y = pack_bf2(h2, h3);
        uint2 lp; lp.x = pack_bf2(l0, l1); lp.y = pack_bf2(l2, l3);
        *(uint2*)(Ath + sw) = hp;
        *(uint2*)(Atl + sw) = lp;
    }

    for (int c = 0; c < 32; c++) {
        const uint32_t vb = sb + 32768 + (c & 1) * 16384;
        if (c < 31) {
#pragma unroll
            for (int t = 0; t < 8; t++) {
                int idx = tid + t * 256;
                int r = idx >> 4, q = idx & 15;
                ar[t] = *(const float4*)(Ab + (size_t)r * L_ + (c + 1) * 64 + q * 4);
            }
            const uint32_t vn = sb + 32768 + ((c + 1) & 1) * 16384;
            cpa_tile<64>(vn,        Vbh + (size_t)(c + 1) * 64 * D_, D_, tid);
            cpa_tile<64>(vn + 8192, Vbl + (size_t)(c + 1) * 64 * D_, D_, tid);
            CP_COMMIT();
            CP_WAIT(1);
        } else {
            CP_WAIT(0);
        }
        __syncthreads();
        chunk_mma<true>(acc, sb, sb + 16384, vb, vb + 8192, mw, nw, lane);
        __syncthreads();
        if (c < 31) {
#pragma unroll
            for (int t = 0; t < 8; t++) {
                int idx = tid + t * 256;
                int r = idx >> 4, q = idx & 15;
                float4 p;
                p.x = __expf(ar[t].x - sM[r]) * sI[r];
                p.y = __expf(ar[t].y - sM[r]) * sI[r];
                p.z = __expf(ar[t].z - sM[r]) * sI[r];
                p.w = __expf(ar[t].w - sM[r]) * sI[r];
                *(float4*)(Ab + (size_t)r * L_ + (c + 1) * 64 + q * 4) = p;
                bf16 h0 = __float2bfloat16(p.x), h1 = __float2bfloat16(p.y);
                bf16 h2 = __float2bfloat16(p.z), h3 = __float2bfloat16(p.w);
                bf16 l0 = __float2bfloat16(p.x - __bfloat162float(h0));
                bf16 l1 = __float2bfloat16(p.y - __bfloat162float(h1));
                bf16 l2 = __float2bfloat16(p.z - __bfloat162float(h2));
                bf16 l3 = __float2bfloat16(p.w - __bfloat162float(h3));
                uint32_t sw = swz(r, q * 8);
                uint2 hp; hp.x = pack_bf2(h0, h1); hp.y = pack_bf2(h2, h3);
                uint2 lp; lp.x = pack_bf2(l0, l1); lp.y = pack_bf2(l2, l3);
                *(uint2*)(Ath + sw) = hp;
                *(uint2*)(Atl + sw) = lp;
            }
        }
    }

    const int g = lane >> 2, tg = lane & 3;
#pragma unroll
    for (int mf = 0; mf < MF; mf++)
#pragma unroll
        for (int nf = 0; nf < NF; nf++) {
            int m   = m0 + mw + mf * 16 + g;
            int col = nw + nf * 8 + tg * 2;
            size_t i0 = ((size_t)b * L_ + m) * E_ + h * D_ + col;
            size_t i1 = i0 + 8 * E_;
            float x0 = acc[mf][nf][0], y0 = acc[mf][nf][1];
            float x1 = acc[mf][nf][2], y1 = acc[mf][nf][3];
            bf16 hx0 = __float2bfloat16(x0), hy0 = __float2bfloat16(y0);
            bf16 hx1 = __float2bfloat16(x1), hy1 = __float2bfloat16(y1);
            bf16 lx0 = __float2bfloat16(x0 - __bfloat162float(hx0));
            bf16 ly0 = __float2bfloat16(y0 - __bfloat162float(hy0));
            bf16 lx1 = __float2bfloat16(x1 - __bfloat162float(hx1));
            bf16 ly1 = __float2bfloat16(y1 - __bfloat162float(hy1));
            *(uint32_t*)&Ch[i0] = pack_bf2(hx0, hy0);
            *(uint32_t*)&Cl[i0] = pack_bf2(lx0, ly0);
            *(uint32_t*)&Ch[i1] = pack_bf2(hx1, hy1);
            *(uint32_t*)&Cl[i1] = pack_bf2(lx1, ly1);
        }
}

// ---------------------------------------------------------------------------
// Launch
// ---------------------------------------------------------------------------
extern "C" void kernel_launch(void* const* d_in, const int* in_sizes, int n_in,
                              void* d_out, int out_size)
{
    const float* iq = (const float*)d_in[0];
    const float* ik = (const float*)d_in[1];
    const float* iv = (const float*)d_in[2];
    const int*   mk = (const int*)  d_in[3];
    const float* Wq = (const float*)d_in[4];
    const float* bq = (const float*)d_in[5];
    const float* Wk = (const float*)d_in[6];
    const float* bk = (const float*)d_in[7];
    const float* Wv = (const float*)d_in[8];
    const float* bv = (const float*)d_in[9];
    const float* Wo = (const float*)d_in[10];
    const float* bo = (const float*)d_in[11];

    float* o_out = (float*)d_out;
    const long long o_elems   = (long long)MTOK * E_;
    const long long att_elems = (long long)B_ * H_ * L_ * L_;

    bf16 *Qh, *Ql, *Kh, *Kl, *Vh, *Vl, *Xh, *Xl, *Wh, *Wl, *Ch, *Cl;
    uint32_t* Mb;
    float *Smv, *Slv, *Ap;
    cudaGetSymbolAddress((void**)&Qh, g_Qh); cudaGetSymbolAddress((void**)&Ql, g_Ql);
    cudaGetSymbolAddress((void**)&Kh, g_Kh); cudaGetSymbolAddress((void**)&Kl, g_Kl);
    cudaGetSymbolAddress((void**)&Vh, g_Vh); cudaGetSymbolAddress((void**)&Vl, g_Vl);
    cudaGetSymbolAddress((void**)&Xh, g_Xh); cudaGetSymbolAddress((void**)&Xl, g_Xl);
    cudaGetSymbolAddress((void**)&Wh, g_Wh); cudaGetSymbolAddress((void**)&Wl, g_Wl);
    cudaGetSymbolAddress((void**)&Ch, g_Ch); cudaGetSymbolAddress((void**)&Cl, g_Cl);
    cudaGetSymbolAddress((void**)&Mb, g_mbits);
    cudaGetSymbolAddress((void**)&Smv, g_sm); cudaGetSymbolAddress((void**)&Slv, g_sl);
    cudaGetSymbolAddress((void**)&Ap, g_att_fallback);

    float* att = ((long long)out_size >= o_elems + att_elems)
                     ? (o_out + o_elems) : Ap;

    cudaFuncSetAttribute(proj_mma<1>, cudaFuncAttributeMaxDynamicSharedMemorySize, PROJ_SMEM);
    cudaFuncSetAttribute(proj_mma<0>, cudaFuncAttributeMaxDynamicSharedMemorySize, PROJ_SMEM);
    cudaFuncSetAttribute(scores_mma,  cudaFuncAttributeMaxDynamicSharedMemorySize, SCORES_SMEM);
    cudaFuncSetAttribute(av_mma,      cudaFuncAttributeMaxDynamicSharedMemorySize, AV_SMEM);

    const int nx4 = MTOK * E_ / 4;
    const int nw4 = E_ * E_ / 4;
    dim3 gp(E_ / 64, MTOK / 128);    // (16, 64)

    // mask bitfield (independent of projections)
    mask_bits<<<B_ * L_ * L_ / 256, 256>>>(mk, Mb);

    // Q
    conv_hl<<<(nx4 + 255) / 256, 256>>>(iq, Xh, Xl, nx4);
    conv_hl<<<(nw4 + 255) / 256, 256>>>(Wq, Wh, Wl, nw4);
    proj_mma<1><<<gp, 256, PROJ_SMEM>>>(Xh, Xl, Wh, Wl, bq, nullptr, Qh, Ql);
    // K
    conv_hl<<<(nx4 + 255) / 256, 256>>>(ik, Xh, Xl, nx4);
    conv_hl<<<(nw4 + 255) / 256, 256>>>(Wk, Wh, Wl, nw4);
    proj_mma<1><<<gp, 256, PROJ_SMEM>>>(Xh, Xl, Wh, Wl, bk, nullptr, Kh, Kl);
    // V
    conv_hl<<<(nx4 + 255) / 256, 256>>>(iv, Xh, Xl, nx4);
    conv_hl<<<(nw4 + 255) / 256, 256>>>(Wv, Wh, Wl, nw4);
    proj_mma<1><<<gp, 256, PROJ_SMEM>>>(Xh, Xl, Wh, Wl, bv, nullptr, Vh, Vl);

    // scores (+ online softmax stats)
    dim3 gs(L_ / 128, B_ * H_);                 // (16, 64)
    scores_mma<<<gs, 256, SCORES_SMEM>>>(Qh, Ql, Kh, Kl, Mb, att, Smv, Slv);

    // AV (+ normalization, writes attention output)
    av_mma<<<gs, 256, AV_SMEM>>>(att, Vh, Vl, Smv, Slv, Ch, Cl);

    // output projection
    conv_hl<<<(nw4 + 255) / 256, 256>>>(Wo, Wh, Wl, nw4);
    proj_mma<0><<<gp, 256, PROJ_SMEM>>>(Ch, Cl, Wh, Wl, bo, o_out, nullptr, nullptr);
}